// round 4
// baseline (speedup 1.0000x reference)
#include <cuda_runtime.h>
#include <cuda_bf16.h>
#include <math.h>
#include <stdint.h>

// ---------------------------------------------------------------------------
// Problem constants
// ---------------------------------------------------------------------------
#define S_LEN   2048
#define HID     4096
#define Q_LORA  1536
#define KV_LORA 512
#define KV_IN   576
#define NH      16
#define QK_NOPE 128
#define QK_ROPE 64
#define Q_HEAD  192
#define V_DIM   128
#define QB_OUT  (NH * Q_HEAD)            // 3072
#define KVB_OUT (NH * (QK_NOPE + V_DIM)) // 4096
#define RMS_EPS 1e-6f
#define ROPE_BASE 10000.0f

typedef __nv_bfloat16 bf16;

// ---------------------------------------------------------------------------
// Static device scratch
// ---------------------------------------------------------------------------
__device__ float g_qlat_raw[S_LEN * Q_LORA];
__device__ float g_kv      [S_LEN * KV_IN];
__device__ float g_qfull   [S_LEN * QB_OUT];
__device__ float g_kvexp   [S_LEN * KVB_OUT];
__device__ float g_scores  [(size_t)NH * S_LEN * S_LEN];
__device__ float g_O       [NH * S_LEN * V_DIM];

// bf16 split-3 operands: A-side = [hi|lo|hi], B-side = [hi|hi|lo]
__device__ bf16 g_hidden3 [(size_t)S_LEN * 3 * HID];
__device__ bf16 g_wqa3    [(size_t)Q_LORA * 3 * HID];
__device__ bf16 g_wkva3   [(size_t)KV_IN * 3 * HID];
__device__ bf16 g_qlat3   [(size_t)S_LEN * 3 * Q_LORA];
__device__ bf16 g_wqb3    [(size_t)QB_OUT * 3 * Q_LORA];
__device__ bf16 g_ckv3    [(size_t)S_LEN * 3 * KV_LORA];
__device__ bf16 g_wkvb3   [(size_t)KVB_OUT * 3 * KV_LORA];
__device__ bf16 g_Q3      [(size_t)NH * S_LEN * 3 * Q_HEAD];
__device__ bf16 g_K3      [(size_t)NH * S_LEN * 3 * Q_HEAD];
__device__ bf16 g_Vt3     [(size_t)NH * V_DIM * 3 * S_LEN];
__device__ bf16 g_P3      [(size_t)NH * S_LEN * 3 * S_LEN];
__device__ bf16 g_attn3   [(size_t)S_LEN * 3 * (NH * V_DIM)];
__device__ bf16 g_wo3     [(size_t)HID * 3 * (NH * V_DIM)];

// ---------------------------------------------------------------------------
// helpers
// ---------------------------------------------------------------------------
__device__ __forceinline__ uint32_t smem_u32(const void* p) {
    return (uint32_t)__cvta_generic_to_shared(p);
}
__device__ __forceinline__ void ldsm_x4(uint32_t& r0, uint32_t& r1,
                                        uint32_t& r2, uint32_t& r3, uint32_t addr) {
    asm volatile("ldmatrix.sync.aligned.m8n8.x4.shared.b16 {%0,%1,%2,%3}, [%4];"
                 : "=r"(r0), "=r"(r1), "=r"(r2), "=r"(r3) : "r"(addr));
}
__device__ __forceinline__ void ldsm_x2(uint32_t& r0, uint32_t& r1, uint32_t addr) {
    asm volatile("ldmatrix.sync.aligned.m8n8.x2.shared.b16 {%0,%1}, [%2];"
                 : "=r"(r0), "=r"(r1) : "r"(addr));
}
__device__ __forceinline__ void mma16816(float* c, const uint32_t* a, const uint32_t* b) {
    asm volatile("mma.sync.aligned.m16n8k16.row.col.f32.bf16.bf16.f32 "
                 "{%0,%1,%2,%3}, {%4,%5,%6,%7}, {%8,%9}, {%0,%1,%2,%3};"
                 : "+f"(c[0]), "+f"(c[1]), "+f"(c[2]), "+f"(c[3])
                 : "r"(a[0]), "r"(a[1]), "r"(a[2]), "r"(a[3]),
                   "r"(b[0]), "r"(b[1]));
}
__device__ __forceinline__ void cp16(uint32_t dst, const void* src, bool pred) {
    int sz = pred ? 16 : 0;
    asm volatile("cp.async.cg.shared.global [%0], [%1], 16, %2;"
                 :: "r"(dst), "l"(src), "r"(sz) : "memory");
}
__device__ __forceinline__ void cp_commit() {
    asm volatile("cp.async.commit_group;" ::: "memory");
}
__device__ __forceinline__ void cp_wait1() {
    asm volatile("cp.async.wait_group 1;" ::: "memory");
}
__device__ __forceinline__ void split2(float v, bf16& h, bf16& l) {
    h = __float2bfloat16(v);
    l = __float2bfloat16(v - __bfloat162float(h));
}

// ---------------------------------------------------------------------------
// bf16 TN GEMM with cp.async 3-stage pipeline.
// C[m,n] = sum_k A[m,k]*B[n,k]; A[M,K] bf16, B[N,K] bf16, C[M,N] fp32.
// CTA 128x128x32, 8 warps (2x4), warp tile 64x32, mma m16n8k16.
// causal=1: skip CTA tile when bn > bm+127 (QK^T).
// pv=1: P*V causal k-tile skip; K = 3*S_LEN in segments of S_LEN, only
//       k-positions <= bm+127 within each segment are used.
// ---------------------------------------------------------------------------
#define SMPAD 40
#define STAGE_BYTES (2 * 128 * SMPAD * 2)   // A+B per stage = 20480
#define GEMM_SMEM (3 * STAGE_BYTES)         // 61440

__global__ __launch_bounds__(256, 2)
void gemm_ca(const bf16* __restrict__ A, const bf16* __restrict__ B,
             float* __restrict__ C, int M, int N, int K,
             long long sA, long long sB, long long sC, int causal, int pv)
{
    const int bm = blockIdx.y * 128;
    const int bn = blockIdx.x * 128;
    if (causal && bn > bm + 127) return;

    A += (long long)blockIdx.z * sA;
    B += (long long)blockIdx.z * sB;
    C += (long long)blockIdx.z * sC;

    extern __shared__ char smem[];
    const uint32_t sb = smem_u32(smem);

    const int tid  = threadIdx.x;
    const int lane = tid & 31;
    const int wid  = tid >> 5;
    const int wm   = (wid >> 2) * 64;
    const int wn   = (wid & 3) * 32;
    const int gid  = lane >> 2;
    const int tig  = lane & 3;

    // loader: row = tid>>1 (0..127), two 16B chunks (tid&1)*2, +1
    const int lr  = tid >> 1;
    const int lc0 = (tid & 1) * 2;    // chunk index (16B = 8 halves)

    // k-tile count / mapping
    int per_seg, nt;
    if (pv) {
        per_seg = bm / 32 + 4;
        if (per_seg > S_LEN / 32) per_seg = S_LEN / 32;
        nt = 3 * per_seg;
    } else {
        per_seg = 0;
        nt = K / 32;
    }

    const bool bval = (bn + lr) < N;

    auto issue = [&](int i) {
        int kt = pv ? ((i / per_seg) * (S_LEN / 32) + (i % per_seg)) : i;
        const int k0 = kt * 32;
        const uint32_t sA_ = sb + (uint32_t)(i % 3) * STAGE_BYTES;
        const uint32_t sB_ = sA_ + 128 * SMPAD * 2;
        const bf16* Ap = A + (size_t)(bm + lr) * K + k0 + lc0 * 8;
        const bf16* Bp = B + (size_t)(bn + lr) * K + k0 + lc0 * 8;
        uint32_t da = sA_ + (uint32_t)(lr * SMPAD + lc0 * 8) * 2;
        uint32_t db = sB_ + (uint32_t)(lr * SMPAD + lc0 * 8) * 2;
        cp16(da,      Ap,     true);
        cp16(da + 16, Ap + 8, true);
        cp16(db,      Bp,     bval);
        cp16(db + 16, Bp + 8, bval);
    };

    float acc[4][4][4];
#pragma unroll
    for (int a = 0; a < 4; a++)
#pragma unroll
        for (int b = 0; b < 4; b++)
#pragma unroll
            for (int c = 0; c < 4; c++) acc[a][b][c] = 0.f;

    const int a_row = wm + (lane & 15);
    const int a_col = (lane >> 4) * 8;
    const int b_row = wn + (lane & 7);
    const int b_col = ((lane >> 3) & 1) * 8;

    issue(0); cp_commit();
    if (nt > 1) issue(1);
    cp_commit();

    for (int i = 0; i < nt; i++) {
        cp_wait1();
        __syncthreads();
        if (i + 2 < nt) issue(i + 2);
        cp_commit();

        const uint32_t sA_ = sb + (uint32_t)(i % 3) * STAGE_BYTES;
        const uint32_t sB_ = sA_ + 128 * SMPAD * 2;
#pragma unroll
        for (int ks = 0; ks < 2; ks++) {
            uint32_t af[4][4], bfr[4][2];
#pragma unroll
            for (int mt = 0; mt < 4; mt++) {
                uint32_t addr = sA_ +
                    (uint32_t)(((a_row + mt * 16) * SMPAD + ks * 16 + a_col) * 2);
                ldsm_x4(af[mt][0], af[mt][1], af[mt][2], af[mt][3], addr);
            }
#pragma unroll
            for (int ntl = 0; ntl < 4; ntl++) {
                uint32_t addr = sB_ +
                    (uint32_t)(((b_row + ntl * 8) * SMPAD + ks * 16 + b_col) * 2);
                ldsm_x2(bfr[ntl][0], bfr[ntl][1], addr);
            }
#pragma unroll
            for (int mt = 0; mt < 4; mt++)
#pragma unroll
                for (int ntl = 0; ntl < 4; ntl++)
                    mma16816(acc[mt][ntl], af[mt], bfr[ntl]);
        }
        __syncthreads();
    }

    // epilogue
#pragma unroll
    for (int mt = 0; mt < 4; mt++) {
        const int row = bm + wm + mt * 16 + gid;
#pragma unroll
        for (int ntl = 0; ntl < 4; ntl++) {
            const int col = bn + wn + ntl * 8 + tig * 2;
            if (col < N) {
                *(float2*)&C[(size_t)row * N + col] =
                    make_float2(acc[mt][ntl][0], acc[mt][ntl][1]);
                *(float2*)&C[(size_t)(row + 8) * N + col] =
                    make_float2(acc[mt][ntl][2], acc[mt][ntl][3]);
            }
        }
    }
}

// ---------------------------------------------------------------------------
// fp32 -> bf16 split-3 (aside=1: [hi|lo|hi], aside=0: [hi|hi|lo])
// ---------------------------------------------------------------------------
__global__ __launch_bounds__(256)
void split3_kernel(const float* __restrict__ x, bf16* __restrict__ y,
                   long long R, long long C, int aside)
{
    const long long n = R * C;
    for (long long i = (long long)blockIdx.x * blockDim.x + threadIdx.x; i < n;
         i += (long long)gridDim.x * blockDim.x) {
        long long r = i / C, c = i - r * C;
        bf16 h, l;
        split2(x[i], h, l);
        bf16* row = y + r * 3 * C;
        row[c]         = h;
        row[C + c]     = aside ? l : h;
        row[2 * C + c] = aside ? h : l;
    }
}

// ---------------------------------------------------------------------------
// RMSNorm fused with A-side split-3 output
// ---------------------------------------------------------------------------
__global__ __launch_bounds__(256)
void rmsnorm_split(const float* __restrict__ x, const float* __restrict__ w,
                   bf16* __restrict__ y3, int len, int xstride)
{
    const int row = blockIdx.x;
    const float* xr = x + (size_t)row * xstride;
    bf16* yr = y3 + (size_t)row * 3 * len;

    float ss = 0.f;
    for (int j = threadIdx.x; j < len; j += 256) { float v = xr[j]; ss += v * v; }
    __shared__ float red[256];
    red[threadIdx.x] = ss;
    __syncthreads();
    for (int s = 128; s > 0; s >>= 1) {
        if (threadIdx.x < s) red[threadIdx.x] += red[threadIdx.x + s];
        __syncthreads();
    }
    const float inv = rsqrtf(red[0] / (float)len + RMS_EPS);
    for (int j = threadIdx.x; j < len; j += 256) {
        bf16 h, l;
        split2(w[j] * xr[j] * inv, h, l);
        yr[j] = h; yr[len + j] = l; yr[2 * len + j] = h;
    }
}

// ---------------------------------------------------------------------------
// RoPE helper
// ---------------------------------------------------------------------------
__device__ __forceinline__ void rope_cs(int pos, int jj, float& c, float& s)
{
    int i = jj & 31;
    float inv = __expf(-((float)(2 * i) / (float)QK_ROPE) * logf(ROPE_BASE));
    float ang = (float)pos * inv;
    c = cosf(ang);
    s = sinf(ang);
}

__global__ void assemble_q(float scale)
{
    const int s = blockIdx.x, h = blockIdx.y, j = threadIdx.x;
    const float* src = g_qfull + (size_t)s * QB_OUT + h * Q_HEAD;
    float v = src[j];
    if (j >= QK_NOPE) {
        int jj = j - QK_NOPE;
        float c, sn;
        rope_cs(s, jj, c, sn);
        float other = (jj < 32) ? -src[QK_NOPE + jj + 32] : src[QK_NOPE + jj - 32];
        v = v * c + other * sn;
    }
    v *= scale;
    bf16 hh, ll;
    split2(v, hh, ll);
    bf16* dst = g_Q3 + ((size_t)h * S_LEN + s) * 3 * Q_HEAD;
    dst[j] = hh; dst[Q_HEAD + j] = ll; dst[2 * Q_HEAD + j] = hh;
}

__global__ void assemble_k()
{
    const int s = blockIdx.x, h = blockIdx.y, j = threadIdx.x;
    float v;
    if (j < QK_NOPE) {
        v = g_kvexp[(size_t)s * KVB_OUT + h * (QK_NOPE + V_DIM) + j];
    } else {
        int jj = j - QK_NOPE;
        const float* pe = g_kv + (size_t)s * KV_IN + KV_LORA;
        float c, sn;
        rope_cs(s, jj, c, sn);
        float other = (jj < 32) ? -pe[jj + 32] : pe[jj - 32];
        v = pe[jj] * c + other * sn;
    }
    bf16 hh, ll;
    split2(v, hh, ll);
    bf16* dst = g_K3 + ((size_t)h * S_LEN + s) * 3 * Q_HEAD;
    dst[j] = hh; dst[Q_HEAD + j] = hh; dst[2 * Q_HEAD + j] = ll;
}

__global__ void assemble_vt()
{
    __shared__ float sm[32][33];
    const int h = blockIdx.z;
    const int s0 = blockIdx.x * 32, d0 = blockIdx.y * 32;
    const int tx = threadIdx.x, ty = threadIdx.y;
    sm[ty][tx] = g_kvexp[(size_t)(s0 + ty) * KVB_OUT +
                         h * (QK_NOPE + V_DIM) + QK_NOPE + d0 + tx];
    __syncthreads();
    const int d = d0 + ty, s = s0 + tx;
    bf16 hh, ll;
    split2(sm[tx][ty], hh, ll);
    bf16* dst = g_Vt3 + ((size_t)h * V_DIM + d) * 3 * S_LEN;
    dst[s] = hh; dst[S_LEN + s] = hh; dst[2 * S_LEN + s] = ll;
}

// ---------------------------------------------------------------------------
// Causal softmax: fp32 scores -> A-side split P3 (exp cached in regs).
// Zero-fills only [L, bm+128) — the PV GEMM never reads past bm+127.
// ---------------------------------------------------------------------------
__global__ __launch_bounds__(256)
void softmax_split()
{
    const int q = blockIdx.x, h = blockIdx.y;
    const float* row = g_scores + ((size_t)h * S_LEN + q) * S_LEN;
    bf16* prow = g_P3 + ((size_t)h * S_LEN + q) * 3 * S_LEN;
    const int L = q + 1;

    __shared__ float red[256];

    float m = -1e30f;
    for (int j = threadIdx.x; j < L; j += 256) m = fmaxf(m, row[j]);
    red[threadIdx.x] = m;
    __syncthreads();
    for (int s = 128; s > 0; s >>= 1) {
        if (threadIdx.x < s)
            red[threadIdx.x] = fmaxf(red[threadIdx.x], red[threadIdx.x + s]);
        __syncthreads();
    }
    m = red[0];
    __syncthreads();

    float ev[8];
    int cnt = 0;
    float sum = 0.f;
    for (int j = threadIdx.x; j < L; j += 256) {
        float e = __expf(row[j] - m);
        ev[cnt++] = e;
        sum += e;
    }
    red[threadIdx.x] = sum;
    __syncthreads();
    for (int s = 128; s > 0; s >>= 1) {
        if (threadIdx.x < s) red[threadIdx.x] += red[threadIdx.x + s];
        __syncthreads();
    }
    const float invs = 1.f / red[0];

    cnt = 0;
    for (int j = threadIdx.x; j < L; j += 256) {
        bf16 hh, ll;
        split2(ev[cnt++] * invs, hh, ll);
        prow[j] = hh; prow[S_LEN + j] = ll; prow[2 * S_LEN + j] = hh;
    }
    const int kz = ((q >> 7) << 7) + 128;   // block end; PV reads no further
    bf16 z = __float2bfloat16(0.f);
    for (int j = L + threadIdx.x; j < kz; j += 256) {
        prow[j] = z; prow[S_LEN + j] = z; prow[2 * S_LEN + j] = z;
    }
}

__global__ void transpose_attn_split()
{
    const int s = blockIdx.x, h = blockIdx.y, d = threadIdx.x;
    float v = g_O[((size_t)h * S_LEN + s) * V_DIM + d];
    bf16 hh, ll;
    split2(v, hh, ll);
    bf16* dst = g_attn3 + (size_t)s * 3 * (NH * V_DIM);
    const int c = h * V_DIM + d;
    dst[c] = hh;
    dst[NH * V_DIM + c] = ll;
    dst[2 * NH * V_DIM + c] = hh;
}

// ---------------------------------------------------------------------------
// Host launch
// ---------------------------------------------------------------------------
extern "C" void kernel_launch(void* const* d_in, const int* in_sizes, int n_in,
                              void* d_out, int out_size)
{
    (void)in_sizes; (void)n_in; (void)out_size;
    const float* hidden = (const float*)d_in[0];
    const float* wq_a   = (const float*)d_in[2];
    const float* qnw    = (const float*)d_in[3];
    const float* wq_b   = (const float*)d_in[4];
    const float* wkv_a  = (const float*)d_in[5];
    const float* kvnw   = (const float*)d_in[6];
    const float* wkv_b  = (const float*)d_in[7];
    const float* wo     = (const float*)d_in[8];
    float* out = (float*)d_out;

    float *qlat_raw, *kv, *qfull, *kvexp, *scores, *O;
    bf16 *hidden3, *wqa3, *wkva3, *qlat3, *wqb3, *ckv3, *wkvb3;
    bf16 *Q3, *K3, *Vt3, *P3, *attn3, *wo3;
    cudaGetSymbolAddress((void**)&qlat_raw, g_qlat_raw);
    cudaGetSymbolAddress((void**)&kv,       g_kv);
    cudaGetSymbolAddress((void**)&qfull,    g_qfull);
    cudaGetSymbolAddress((void**)&kvexp,    g_kvexp);
    cudaGetSymbolAddress((void**)&scores,   g_scores);
    cudaGetSymbolAddress((void**)&O,        g_O);
    cudaGetSymbolAddress((void**)&hidden3,  g_hidden3);
    cudaGetSymbolAddress((void**)&wqa3,     g_wqa3);
    cudaGetSymbolAddress((void**)&wkva3,    g_wkva3);
    cudaGetSymbolAddress((void**)&qlat3,    g_qlat3);
    cudaGetSymbolAddress((void**)&wqb3,     g_wqb3);
    cudaGetSymbolAddress((void**)&ckv3,     g_ckv3);
    cudaGetSymbolAddress((void**)&wkvb3,    g_wkvb3);
    cudaGetSymbolAddress((void**)&Q3,       g_Q3);
    cudaGetSymbolAddress((void**)&K3,       g_K3);
    cudaGetSymbolAddress((void**)&Vt3,      g_Vt3);
    cudaGetSymbolAddress((void**)&P3,       g_P3);
    cudaGetSymbolAddress((void**)&attn3,    g_attn3);
    cudaGetSymbolAddress((void**)&wo3,      g_wo3);

    const float softmax_scale = rsqrtf((float)Q_HEAD);
    dim3 blk(256);

    cudaFuncSetAttribute(gemm_ca, cudaFuncAttributeMaxDynamicSharedMemorySize,
                         GEMM_SMEM);

    // splits of inputs / weights
    split3_kernel<<<1024, 256>>>(hidden, hidden3, S_LEN, HID, 1);
    split3_kernel<<<1024, 256>>>(wq_a,  wqa3,  Q_LORA,  HID, 0);
    split3_kernel<<<1024, 256>>>(wkv_a, wkva3, KV_IN,   HID, 0);
    split3_kernel<<<1024, 256>>>(wq_b,  wqb3,  QB_OUT,  Q_LORA, 0);
    split3_kernel<<<1024, 256>>>(wkv_b, wkvb3, KVB_OUT, KV_LORA, 0);
    split3_kernel<<<1024, 256>>>(wo,    wo3,   HID,     NH * V_DIM, 0);

    // 1. q_lat_raw = hidden @ wq_a^T
    gemm_ca<<<dim3(Q_LORA / 128, S_LEN / 128, 1), blk, GEMM_SMEM>>>(
        hidden3, wqa3, qlat_raw, S_LEN, Q_LORA, 3 * HID, 0, 0, 0, 0, 0);
    // 2. kv = hidden @ wkv_a^T (N=576 guarded)
    gemm_ca<<<dim3((KV_IN + 127) / 128, S_LEN / 128, 1), blk, GEMM_SMEM>>>(
        hidden3, wkva3, kv, S_LEN, KV_IN, 3 * HID, 0, 0, 0, 0, 0);
    // 3-4. RMSNorms with fused split
    rmsnorm_split<<<S_LEN, 256>>>(qlat_raw, qnw, qlat3, Q_LORA, Q_LORA);
    rmsnorm_split<<<S_LEN, 256>>>(kv, kvnw, ckv3, KV_LORA, KV_IN);
    // 5. q = q_lat @ wq_b^T
    gemm_ca<<<dim3(QB_OUT / 128, S_LEN / 128, 1), blk, GEMM_SMEM>>>(
        qlat3, wqb3, qfull, S_LEN, QB_OUT, 3 * Q_LORA, 0, 0, 0, 0, 0);
    // 6. kv_exp = ckv @ wkv_b^T
    gemm_ca<<<dim3(KVB_OUT / 128, S_LEN / 128, 1), blk, GEMM_SMEM>>>(
        ckv3, wkvb3, kvexp, S_LEN, KVB_OUT, 3 * KV_LORA, 0, 0, 0, 0, 0);
    // 7-9. assemble split operands
    assemble_q<<<dim3(S_LEN, NH), Q_HEAD>>>(softmax_scale);
    assemble_k<<<dim3(S_LEN, NH), Q_HEAD>>>();
    assemble_vt<<<dim3(S_LEN / 32, V_DIM / 32, NH), dim3(32, 32)>>>();
    // 10. scores = Q @ K^T (causal block skip)
    gemm_ca<<<dim3(S_LEN / 128, S_LEN / 128, NH), blk, GEMM_SMEM>>>(
        Q3, K3, scores, S_LEN, S_LEN, 3 * Q_HEAD,
        (long long)S_LEN * 3 * Q_HEAD, (long long)S_LEN * 3 * Q_HEAD,
        (long long)S_LEN * S_LEN, 1, 0);
    // 11. causal softmax + split
    softmax_split<<<dim3(S_LEN, NH), 256>>>();
    // 12. O = P @ V (causal k-tile skip)
    gemm_ca<<<dim3(1, S_LEN / 128, NH), blk, GEMM_SMEM>>>(
        P3, Vt3, O, S_LEN, V_DIM, 3 * S_LEN,
        (long long)S_LEN * 3 * S_LEN, (long long)V_DIM * 3 * S_LEN,
        (long long)S_LEN * V_DIM, 0, 1);
    // 13. flatten heads + split
    transpose_attn_split<<<dim3(S_LEN, NH), V_DIM>>>();
    // 14. out = attn @ wo^T
    gemm_ca<<<dim3(HID / 128, S_LEN / 128, 1), blk, GEMM_SMEM>>>(
        attn3, wo3, out, S_LEN, HID, 3 * NH * V_DIM, 0, 0, 0, 0, 0);
}

// round 5
// speedup vs baseline: 1.1287x; 1.1287x over previous
#include <cuda_runtime.h>
#include <cuda_bf16.h>
#include <math.h>
#include <stdint.h>

// ---------------------------------------------------------------------------
// Problem constants
// ---------------------------------------------------------------------------
#define S_LEN   2048
#define HID     4096
#define Q_LORA  1536
#define KV_LORA 512
#define KV_IN   576
#define NH      16
#define QK_NOPE 128
#define QK_ROPE 64
#define Q_HEAD  192
#define V_DIM   128
#define QB_OUT  (NH * Q_HEAD)            // 3072
#define KVB_OUT (NH * (QK_NOPE + V_DIM)) // 4096
#define RMS_EPS 1e-6f
#define ROPE_BASE 10000.0f

typedef __nv_bfloat16 bf16;

// ---------------------------------------------------------------------------
// Static device scratch
// ---------------------------------------------------------------------------
__device__ float g_qlat_raw[S_LEN * Q_LORA];
__device__ float g_kv      [S_LEN * KV_IN];
__device__ float g_qfull   [S_LEN * QB_OUT];
__device__ float g_kvexp   [S_LEN * KVB_OUT];
__device__ float g_scores  [(size_t)NH * S_LEN * S_LEN];
__device__ float g_O       [NH * S_LEN * V_DIM];

// bf16 split-3 operands: A-side = [hi|lo|hi], B-side = [hi|hi|lo]
__device__ bf16 g_hidden3 [(size_t)S_LEN * 3 * HID];
__device__ bf16 g_wqa3    [(size_t)Q_LORA * 3 * HID];
__device__ bf16 g_wkva3   [(size_t)KV_IN * 3 * HID];
__device__ bf16 g_qlat3   [(size_t)S_LEN * 3 * Q_LORA];
__device__ bf16 g_wqb3    [(size_t)QB_OUT * 3 * Q_LORA];
__device__ bf16 g_ckv3    [(size_t)S_LEN * 3 * KV_LORA];
__device__ bf16 g_wkvb3   [(size_t)KVB_OUT * 3 * KV_LORA];
__device__ bf16 g_Q3      [(size_t)NH * S_LEN * 3 * Q_HEAD];
__device__ bf16 g_K3      [(size_t)NH * S_LEN * 3 * Q_HEAD];
__device__ bf16 g_Vt3     [(size_t)NH * V_DIM * 3 * S_LEN];
__device__ bf16 g_P3      [(size_t)NH * S_LEN * 3 * S_LEN];
__device__ bf16 g_attn3   [(size_t)S_LEN * 3 * (NH * V_DIM)];
__device__ bf16 g_wo3     [(size_t)HID * 3 * (NH * V_DIM)];

// ---------------------------------------------------------------------------
// helpers
// ---------------------------------------------------------------------------
__device__ __forceinline__ uint32_t smem_u32(const void* p) {
    return (uint32_t)__cvta_generic_to_shared(p);
}
__device__ __forceinline__ void ldsm_x4(uint32_t& r0, uint32_t& r1,
                                        uint32_t& r2, uint32_t& r3, uint32_t addr) {
    asm volatile("ldmatrix.sync.aligned.m8n8.x4.shared.b16 {%0,%1,%2,%3}, [%4];"
                 : "=r"(r0), "=r"(r1), "=r"(r2), "=r"(r3) : "r"(addr));
}
__device__ __forceinline__ void ldsm_x2(uint32_t& r0, uint32_t& r1, uint32_t addr) {
    asm volatile("ldmatrix.sync.aligned.m8n8.x2.shared.b16 {%0,%1}, [%2];"
                 : "=r"(r0), "=r"(r1) : "r"(addr));
}
__device__ __forceinline__ void mma16816(float* c, const uint32_t* a, const uint32_t* b) {
    asm volatile("mma.sync.aligned.m16n8k16.row.col.f32.bf16.bf16.f32 "
                 "{%0,%1,%2,%3}, {%4,%5,%6,%7}, {%8,%9}, {%0,%1,%2,%3};"
                 : "+f"(c[0]), "+f"(c[1]), "+f"(c[2]), "+f"(c[3])
                 : "r"(a[0]), "r"(a[1]), "r"(a[2]), "r"(a[3]),
                   "r"(b[0]), "r"(b[1]));
}
__device__ __forceinline__ void split2(float v, bf16& h, bf16& l) {
    h = __float2bfloat16(v);
    l = __float2bfloat16(v - __bfloat162float(h));
}

// ---------------------------------------------------------------------------
// bf16 TN GEMM (round-2 proven core): C[m,n] = sum_k A[m,k]*B[n,k].
// A [M,K] bf16, B [N,K] bf16, C fp32 [M,N]. CTA 128x128x32, 8 warps,
// register double-buffer, one __syncthreads per K-tile.
// causal=1: skip CTA tile when bn > bm+127 (QK^T).
// pv=1: causal k-tile skip for P*V. K = 3*S_LEN in 3 segments; only
//       k-positions < bm+128 in each segment contribute.
// ---------------------------------------------------------------------------
#define GBM 128
#define GBK 32
#define SMPAD 40   // row stride in halves (conflict-free, 16B-aligned)

__global__ __launch_bounds__(256)
void gemm_bf16_tn(const bf16* __restrict__ A, const bf16* __restrict__ B,
                  float* __restrict__ C, int M, int N, int K,
                  long long sA, long long sB, long long sC, int causal, int pv)
{
    const int bm = blockIdx.y * GBM;
    const int bn = blockIdx.x * GBM;
    if (causal && bn > bm + GBM - 1) return;   // dead causal block

    A += (long long)blockIdx.z * sA;
    B += (long long)blockIdx.z * sB;
    C += (long long)blockIdx.z * sC;

    __shared__ bf16 As[2][GBM][SMPAD];
    __shared__ bf16 Bs[2][GBM][SMPAD];

    const int tid  = threadIdx.x;
    const int lane = tid & 31;
    const int wid  = tid >> 5;
    const int wm   = (wid >> 2) * 64;   // warp m offset (0,64)
    const int wn   = (wid & 3) * 32;    // warp n offset (0..96)
    const int gid  = lane >> 2;
    const int tig  = lane & 3;

    const int lr = tid >> 2;            // 0..63
    const int lc = (tid & 3) * 8;       // 0,8,16,24

    float acc[4][4][4];
#pragma unroll
    for (int a = 0; a < 4; a++)
#pragma unroll
        for (int b = 0; b < 4; b++)
#pragma unroll
            for (int c = 0; c < 4; c++) acc[a][b][c] = 0.f;

    // k-tile count / mapping (pv: skip dead causal k-tiles per segment)
    int per_seg, ntiles;
    if (pv) {
        per_seg = bm / GBK + 4;                       // tiles covering k < bm+128
        if (per_seg > S_LEN / GBK) per_seg = S_LEN / GBK;
        ntiles = 3 * per_seg;
    } else {
        per_seg = 0;
        ntiles = K / GBK;
    }

    const bool aval = (bm + lr) < M;
    const bool bval = (bn + lr) < N;

    uint4 av0, av1, bv0, bv1;
    auto glob_load = [&](int i) {
        const int kt = pv ? ((i / per_seg) * (S_LEN / GBK) + (i % per_seg)) : i;
        const int k0 = kt * GBK;
        const bf16* Ap = A + (size_t)(bm + lr) * K + k0 + lc;
        av0 = aval ? *(const uint4*)Ap                    : make_uint4(0,0,0,0);
        av1 = aval ? *(const uint4*)(Ap + (size_t)64 * K) : make_uint4(0,0,0,0);
        const int n0 = bn + lr;
        const bf16* Bp = B + (size_t)n0 * K + k0 + lc;
        bv0 = (n0      < N) ? *(const uint4*)Bp                    : make_uint4(0,0,0,0);
        bv1 = (n0 + 64 < N) ? *(const uint4*)(Bp + (size_t)64 * K) : make_uint4(0,0,0,0);
    };
    auto sts = [&](int buf) {
        *(uint4*)&As[buf][lr     ][lc] = av0;
        *(uint4*)&As[buf][lr + 64][lc] = av1;
        *(uint4*)&Bs[buf][lr     ][lc] = bv0;
        *(uint4*)&Bs[buf][lr + 64][lc] = bv1;
    };

    const uint32_t as_base = smem_u32(&As[0][0][0]);
    const uint32_t bs_base = smem_u32(&Bs[0][0][0]);
    const uint32_t BUFB = GBM * SMPAD * 2;   // bytes per buffer

    const int a_row = wm + (lane & 15);
    const int a_col = (lane >> 4) * 8;
    const int b_row = wn + (lane & 7);
    const int b_col = ((lane >> 3) & 1) * 8;

    auto compute = [&](int buf) {
#pragma unroll
        for (int ks = 0; ks < 2; ks++) {
            uint32_t af[4][4], bfr[4][2];
#pragma unroll
            for (int mt = 0; mt < 4; mt++) {
                uint32_t addr = as_base + buf * BUFB +
                    (uint32_t)(((a_row + mt * 16) * SMPAD + ks * 16 + a_col) * 2);
                ldsm_x4(af[mt][0], af[mt][1], af[mt][2], af[mt][3], addr);
            }
#pragma unroll
            for (int nt = 0; nt < 4; nt++) {
                uint32_t addr = bs_base + buf * BUFB +
                    (uint32_t)(((b_row + nt * 8) * SMPAD + ks * 16 + b_col) * 2);
                ldsm_x2(bfr[nt][0], bfr[nt][1], addr);
            }
#pragma unroll
            for (int mt = 0; mt < 4; mt++)
#pragma unroll
                for (int nt = 0; nt < 4; nt++)
                    mma16816(acc[mt][nt], af[mt], bfr[nt]);
        }
    };

    glob_load(0);
    sts(0);
    __syncthreads();
    int buf = 0;
    for (int kt = 0; kt < ntiles; kt++) {
        if (kt + 1 < ntiles) glob_load(kt + 1);
        compute(buf);
        if (kt + 1 < ntiles) {
            sts(buf ^ 1);
            __syncthreads();
            buf ^= 1;
        }
    }

    // epilogue
#pragma unroll
    for (int mt = 0; mt < 4; mt++) {
        const int row = bm + wm + mt * 16 + gid;
        if (row < M) {
#pragma unroll
            for (int nt = 0; nt < 4; nt++) {
                const int col = bn + wn + nt * 8 + tig * 2;
                if (col < N) {
                    *(float2*)&C[(size_t)row * N + col] =
                        make_float2(acc[mt][nt][0], acc[mt][nt][1]);
                    *(float2*)&C[(size_t)(row + 8) * N + col] =
                        make_float2(acc[mt][nt][2], acc[mt][nt][3]);
                }
            }
        }
    }
}

// ---------------------------------------------------------------------------
// fp32 -> bf16 split-3 (aside=1: [hi|lo|hi], aside=0: [hi|hi|lo])
// ---------------------------------------------------------------------------
__global__ __launch_bounds__(256)
void split3_kernel(const float* __restrict__ x, bf16* __restrict__ y,
                   long long R, long long C, int aside)
{
    const long long n = R * C;
    for (long long i = (long long)blockIdx.x * blockDim.x + threadIdx.x; i < n;
         i += (long long)gridDim.x * blockDim.x) {
        long long r = i / C, c = i - r * C;
        bf16 h, l;
        split2(x[i], h, l);
        bf16* row = y + r * 3 * C;
        row[c]         = h;
        row[C + c]     = aside ? l : h;
        row[2 * C + c] = aside ? h : l;
    }
}

// ---------------------------------------------------------------------------
// RMSNorm fused with A-side split-3 output
// ---------------------------------------------------------------------------
__global__ __launch_bounds__(256)
void rmsnorm_split(const float* __restrict__ x, const float* __restrict__ w,
                   bf16* __restrict__ y3, int len, int xstride)
{
    const int row = blockIdx.x;
    const float* xr = x + (size_t)row * xstride;
    bf16* yr = y3 + (size_t)row * 3 * len;

    float ss = 0.f;
    for (int j = threadIdx.x; j < len; j += 256) { float v = xr[j]; ss += v * v; }
    __shared__ float red[256];
    red[threadIdx.x] = ss;
    __syncthreads();
    for (int s = 128; s > 0; s >>= 1) {
        if (threadIdx.x < s) red[threadIdx.x] += red[threadIdx.x + s];
        __syncthreads();
    }
    const float inv = rsqrtf(red[0] / (float)len + RMS_EPS);
    for (int j = threadIdx.x; j < len; j += 256) {
        bf16 h, l;
        split2(w[j] * xr[j] * inv, h, l);
        yr[j] = h; yr[len + j] = l; yr[2 * len + j] = h;
    }
}

// ---------------------------------------------------------------------------
// RoPE helper
// ---------------------------------------------------------------------------
__device__ __forceinline__ void rope_cs(int pos, int jj, float& c, float& s)
{
    int i = jj & 31;
    float inv = __expf(-((float)(2 * i) / (float)QK_ROPE) * logf(ROPE_BASE));
    float ang = (float)pos * inv;
    c = cosf(ang);
    s = sinf(ang);
}

__global__ void assemble_q(float scale)
{
    const int s = blockIdx.x, h = blockIdx.y, j = threadIdx.x;
    const float* src = g_qfull + (size_t)s * QB_OUT + h * Q_HEAD;
    float v = src[j];
    if (j >= QK_NOPE) {
        int jj = j - QK_NOPE;
        float c, sn;
        rope_cs(s, jj, c, sn);
        float other = (jj < 32) ? -src[QK_NOPE + jj + 32] : src[QK_NOPE + jj - 32];
        v = v * c + other * sn;
    }
    v *= scale;
    bf16 hh, ll;
    split2(v, hh, ll);
    bf16* dst = g_Q3 + ((size_t)h * S_LEN + s) * 3 * Q_HEAD;
    dst[j] = hh; dst[Q_HEAD + j] = ll; dst[2 * Q_HEAD + j] = hh;
}

__global__ void assemble_k()
{
    const int s = blockIdx.x, h = blockIdx.y, j = threadIdx.x;
    float v;
    if (j < QK_NOPE) {
        v = g_kvexp[(size_t)s * KVB_OUT + h * (QK_NOPE + V_DIM) + j];
    } else {
        int jj = j - QK_NOPE;
        const float* pe = g_kv + (size_t)s * KV_IN + KV_LORA;
        float c, sn;
        rope_cs(s, jj, c, sn);
        float other = (jj < 32) ? -pe[jj + 32] : pe[jj - 32];
        v = pe[jj] * c + other * sn;
    }
    bf16 hh, ll;
    split2(v, hh, ll);
    bf16* dst = g_K3 + ((size_t)h * S_LEN + s) * 3 * Q_HEAD;
    dst[j] = hh; dst[Q_HEAD + j] = hh; dst[2 * Q_HEAD + j] = ll;
}

__global__ void assemble_vt()
{
    __shared__ float sm[32][33];
    const int h = blockIdx.z;
    const int s0 = blockIdx.x * 32, d0 = blockIdx.y * 32;
    const int tx = threadIdx.x, ty = threadIdx.y;
    sm[ty][tx] = g_kvexp[(size_t)(s0 + ty) * KVB_OUT +
                         h * (QK_NOPE + V_DIM) + QK_NOPE + d0 + tx];
    __syncthreads();
    const int d = d0 + ty, s = s0 + tx;
    bf16 hh, ll;
    split2(sm[tx][ty], hh, ll);
    bf16* dst = g_Vt3 + ((size_t)h * V_DIM + d) * 3 * S_LEN;
    dst[s] = hh; dst[S_LEN + s] = hh; dst[2 * S_LEN + s] = ll;
}

// ---------------------------------------------------------------------------
// Causal softmax: fp32 scores -> A-side split P3.
// exp cached in regs; zero-fill only to the 128-block end (PV reads no further).
// ---------------------------------------------------------------------------
__global__ __launch_bounds__(256)
void softmax_split()
{
    const int q = blockIdx.x, h = blockIdx.y;
    const float* row = g_scores + ((size_t)h * S_LEN + q) * S_LEN;
    bf16* prow = g_P3 + ((size_t)h * S_LEN + q) * 3 * S_LEN;
    const int L = q + 1;

    __shared__ float red[256];

    float m = -1e30f;
    for (int j = threadIdx.x; j < L; j += 256) m = fmaxf(m, row[j]);
    red[threadIdx.x] = m;
    __syncthreads();
    for (int s = 128; s > 0; s >>= 1) {
        if (threadIdx.x < s)
            red[threadIdx.x] = fmaxf(red[threadIdx.x], red[threadIdx.x + s]);
        __syncthreads();
    }
    m = red[0];
    __syncthreads();

    float ev[8];
    int cnt = 0;
    float sum = 0.f;
    for (int j = threadIdx.x; j < L; j += 256) {
        float e = __expf(row[j] - m);
        ev[cnt++] = e;
        sum += e;
    }
    red[threadIdx.x] = sum;
    __syncthreads();
    for (int s = 128; s > 0; s >>= 1) {
        if (threadIdx.x < s) red[threadIdx.x] += red[threadIdx.x + s];
        __syncthreads();
    }
    const float invs = 1.f / red[0];

    cnt = 0;
    for (int j = threadIdx.x; j < L; j += 256) {
        bf16 hh, ll;
        split2(ev[cnt++] * invs, hh, ll);
        prow[j] = hh; prow[S_LEN + j] = ll; prow[2 * S_LEN + j] = hh;
    }
    const int kz = ((q >> 7) << 7) + 128;   // PV k-tile skip reads no further
    bf16 z = __float2bfloat16(0.f);
    for (int j = L + threadIdx.x; j < kz; j += 256) {
        prow[j] = z; prow[S_LEN + j] = z; prow[2 * S_LEN + j] = z;
    }
}

__global__ void transpose_attn_split()
{
    const int s = blockIdx.x, h = blockIdx.y, d = threadIdx.x;
    float v = g_O[((size_t)h * S_LEN + s) * V_DIM + d];
    bf16 hh, ll;
    split2(v, hh, ll);
    bf16* dst = g_attn3 + (size_t)s * 3 * (NH * V_DIM);
    const int c = h * V_DIM + d;
    dst[c] = hh;
    dst[NH * V_DIM + c] = ll;
    dst[2 * NH * V_DIM + c] = hh;
}

// ---------------------------------------------------------------------------
// Host launch
// ---------------------------------------------------------------------------
extern "C" void kernel_launch(void* const* d_in, const int* in_sizes, int n_in,
                              void* d_out, int out_size)
{
    (void)in_sizes; (void)n_in; (void)out_size;
    const float* hidden = (const float*)d_in[0];
    const float* wq_a   = (const float*)d_in[2];
    const float* qnw    = (const float*)d_in[3];
    const float* wq_b   = (const float*)d_in[4];
    const float* wkv_a  = (const float*)d_in[5];
    const float* kvnw   = (const float*)d_in[6];
    const float* wkv_b  = (const float*)d_in[7];
    const float* wo     = (const float*)d_in[8];
    float* out = (float*)d_out;

    float *qlat_raw, *kv, *qfull, *kvexp, *scores, *O;
    bf16 *hidden3, *wqa3, *wkva3, *qlat3, *wqb3, *ckv3, *wkvb3;
    bf16 *Q3, *K3, *Vt3, *P3, *attn3, *wo3;
    cudaGetSymbolAddress((void**)&qlat_raw, g_qlat_raw);
    cudaGetSymbolAddress((void**)&kv,       g_kv);
    cudaGetSymbolAddress((void**)&qfull,    g_qfull);
    cudaGetSymbolAddress((void**)&kvexp,    g_kvexp);
    cudaGetSymbolAddress((void**)&scores,   g_scores);
    cudaGetSymbolAddress((void**)&O,        g_O);
    cudaGetSymbolAddress((void**)&hidden3,  g_hidden3);
    cudaGetSymbolAddress((void**)&wqa3,     g_wqa3);
    cudaGetSymbolAddress((void**)&wkva3,    g_wkva3);
    cudaGetSymbolAddress((void**)&qlat3,    g_qlat3);
    cudaGetSymbolAddress((void**)&wqb3,     g_wqb3);
    cudaGetSymbolAddress((void**)&ckv3,     g_ckv3);
    cudaGetSymbolAddress((void**)&wkvb3,    g_wkvb3);
    cudaGetSymbolAddress((void**)&Q3,       g_Q3);
    cudaGetSymbolAddress((void**)&K3,       g_K3);
    cudaGetSymbolAddress((void**)&Vt3,      g_Vt3);
    cudaGetSymbolAddress((void**)&P3,       g_P3);
    cudaGetSymbolAddress((void**)&attn3,    g_attn3);
    cudaGetSymbolAddress((void**)&wo3,      g_wo3);

    const float softmax_scale = rsqrtf((float)Q_HEAD);
    dim3 blk(256);

    // splits of inputs / weights
    split3_kernel<<<1024, 256>>>(hidden, hidden3, S_LEN, HID, 1);
    split3_kernel<<<1024, 256>>>(wq_a,  wqa3,  Q_LORA,  HID, 0);
    split3_kernel<<<1024, 256>>>(wkv_a, wkva3, KV_IN,   HID, 0);
    split3_kernel<<<1024, 256>>>(wq_b,  wqb3,  QB_OUT,  Q_LORA, 0);
    split3_kernel<<<1024, 256>>>(wkv_b, wkvb3, KVB_OUT, KV_LORA, 0);
    split3_kernel<<<1024, 256>>>(wo,    wo3,   HID,     NH * V_DIM, 0);

    // 1. q_lat_raw = hidden @ wq_a^T
    gemm_bf16_tn<<<dim3(Q_LORA / 128, S_LEN / 128, 1), blk>>>(
        hidden3, wqa3, qlat_raw, S_LEN, Q_LORA, 3 * HID, 0, 0, 0, 0, 0);
    // 2. kv = hidden @ wkv_a^T  (N=576, guarded)
    gemm_bf16_tn<<<dim3((KV_IN + 127) / 128, S_LEN / 128, 1), blk>>>(
        hidden3, wkva3, kv, S_LEN, KV_IN, 3 * HID, 0, 0, 0, 0, 0);
    // 3-4. RMSNorms with fused split
    rmsnorm_split<<<S_LEN, 256>>>(qlat_raw, qnw, qlat3, Q_LORA, Q_LORA);
    rmsnorm_split<<<S_LEN, 256>>>(kv, kvnw, ckv3, KV_LORA, KV_IN);
    // 5. q = q_lat @ wq_b^T
    gemm_bf16_tn<<<dim3(QB_OUT / 128, S_LEN / 128, 1), blk>>>(
        qlat3, wqb3, qfull, S_LEN, QB_OUT, 3 * Q_LORA, 0, 0, 0, 0, 0);
    // 6. kv_exp = ckv @ wkv_b^T
    gemm_bf16_tn<<<dim3(KVB_OUT / 128, S_LEN / 128, 1), blk>>>(
        ckv3, wkvb3, kvexp, S_LEN, KVB_OUT, 3 * KV_LORA, 0, 0, 0, 0, 0);
    // 7-9. assemble split operands
    assemble_q<<<dim3(S_LEN, NH), Q_HEAD>>>(softmax_scale);
    assemble_k<<<dim3(S_LEN, NH), Q_HEAD>>>();
    assemble_vt<<<dim3(S_LEN / 32, V_DIM / 32, NH), dim3(32, 32)>>>();
    // 10. scores = Q @ K^T (causal blocks skipped)
    gemm_bf16_tn<<<dim3(S_LEN / 128, S_LEN / 128, NH), blk>>>(
        Q3, K3, scores, S_LEN, S_LEN, 3 * Q_HEAD,
        (long long)S_LEN * 3 * Q_HEAD, (long long)S_LEN * 3 * Q_HEAD,
        (long long)S_LEN * S_LEN, 1, 0);
    // 11. causal softmax + split
    softmax_split<<<dim3(S_LEN, NH), 256>>>();
    // 12. O = P @ V (causal k-tile skip)
    gemm_bf16_tn<<<dim3(1, S_LEN / 128, NH), blk>>>(
        P3, Vt3, O, S_LEN, V_DIM, 3 * S_LEN,
        (long long)S_LEN * 3 * S_LEN, (long long)V_DIM * 3 * S_LEN,
        (long long)S_LEN * V_DIM, 0, 1);
    // 13. flatten heads + split
    transpose_attn_split<<<dim3(S_LEN, NH), V_DIM>>>();
    // 14. out = attn @ wo^T
    gemm_bf16_tn<<<dim3(HID / 128, S_LEN / 128, 1), blk>>>(
        attn3, wo3, out, S_LEN, HID, 3 * NH * V_DIM, 0, 0, 0, 0, 0);
}

// round 6
// speedup vs baseline: 1.1692x; 1.0359x over previous
#include <cuda_runtime.h>
#include <cuda_bf16.h>
#include <math.h>
#include <stdint.h>

// ---------------------------------------------------------------------------
// Problem constants
// ---------------------------------------------------------------------------
#define S_LEN   2048
#define HID     4096
#define Q_LORA  1536
#define KV_LORA 512
#define KV_IN   576
#define NH      16
#define QK_NOPE 128
#define QK_ROPE 64
#define Q_HEAD  192
#define V_DIM   128
#define QB_OUT  (NH * Q_HEAD)            // 3072
#define KVB_OUT (NH * (QK_NOPE + V_DIM)) // 4096
#define RMS_EPS 1e-6f
#define ROPE_BASE 10000.0f

typedef __nv_bfloat16 bf16;

// ---------------------------------------------------------------------------
// Static device scratch.
// All split operands stored as [hi|lo] (physical K = 2*Kb). The GEMM issues
// 3 logical segment-products with maps A:{0,1,0}, B:{0,0,1}.
// ---------------------------------------------------------------------------
__device__ float g_qlat_raw[S_LEN * Q_LORA];
__device__ float g_kv      [S_LEN * KV_IN];
__device__ float g_qfull   [S_LEN * QB_OUT];
__device__ float g_kvexp   [S_LEN * KVB_OUT];
__device__ float g_scores  [(size_t)NH * S_LEN * S_LEN];
__device__ float g_O       [NH * S_LEN * V_DIM];

__device__ bf16 g_hidden2 [(size_t)S_LEN * 2 * HID];
__device__ bf16 g_wqa2    [(size_t)Q_LORA * 2 * HID];
__device__ bf16 g_wkva2   [(size_t)KV_IN * 2 * HID];
__device__ bf16 g_qlat2   [(size_t)S_LEN * 2 * Q_LORA];
__device__ bf16 g_wqb2    [(size_t)QB_OUT * 2 * Q_LORA];
__device__ bf16 g_ckv2    [(size_t)S_LEN * 2 * KV_LORA];
__device__ bf16 g_wkvb2   [(size_t)KVB_OUT * 2 * KV_LORA];
__device__ bf16 g_Q2      [(size_t)NH * S_LEN * 2 * Q_HEAD];
__device__ bf16 g_K2      [(size_t)NH * S_LEN * 2 * Q_HEAD];
__device__ bf16 g_Vt2     [(size_t)NH * V_DIM * 2 * S_LEN];
__device__ bf16 g_P2      [(size_t)NH * S_LEN * 2 * S_LEN];
__device__ bf16 g_attn2   [(size_t)S_LEN * 2 * (NH * V_DIM)];
__device__ bf16 g_wo2     [(size_t)HID * 2 * (NH * V_DIM)];

// ---------------------------------------------------------------------------
// helpers
// ---------------------------------------------------------------------------
__device__ __forceinline__ uint32_t smem_u32(const void* p) {
    return (uint32_t)__cvta_generic_to_shared(p);
}
__device__ __forceinline__ void ldsm_x4(uint32_t& r0, uint32_t& r1,
                                        uint32_t& r2, uint32_t& r3, uint32_t addr) {
    asm volatile("ldmatrix.sync.aligned.m8n8.x4.shared.b16 {%0,%1,%2,%3}, [%4];"
                 : "=r"(r0), "=r"(r1), "=r"(r2), "=r"(r3) : "r"(addr));
}
__device__ __forceinline__ void ldsm_x2(uint32_t& r0, uint32_t& r1, uint32_t addr) {
    asm volatile("ldmatrix.sync.aligned.m8n8.x2.shared.b16 {%0,%1}, [%2];"
                 : "=r"(r0), "=r"(r1) : "r"(addr));
}
__device__ __forceinline__ void mma16816(float* c, const uint32_t* a, const uint32_t* b) {
    asm volatile("mma.sync.aligned.m16n8k16.row.col.f32.bf16.bf16.f32 "
                 "{%0,%1,%2,%3}, {%4,%5,%6,%7}, {%8,%9}, {%0,%1,%2,%3};"
                 : "+f"(c[0]), "+f"(c[1]), "+f"(c[2]), "+f"(c[3])
                 : "r"(a[0]), "r"(a[1]), "r"(a[2]), "r"(a[3]),
                   "r"(b[0]), "r"(b[1]));
}
__device__ __forceinline__ void split2(float v, bf16& h, bf16& l) {
    h = __float2bfloat16(v);
    l = __float2bfloat16(v - __bfloat162float(h));
}

// ---------------------------------------------------------------------------
// bf16 TN GEMM, split-2 storage + 3 logical segment products.
// C[m,n] = sum over 3 segments: (Ah,Bh),(Al,Bh),(Ah,Bl) of seg dot products.
// A [M, 2*Kb] bf16 ([hi|lo]), B [N, 2*Kb] bf16 ([hi|lo]), C fp32 [M,N].
// CTA 128x128x32, 8 warps, register double-buffer.
// causal=1: skip CTA tile when bn > bm+127.
// pv=1: causal k-tile skip — only k-positions < bm+128 per segment contribute.
// ---------------------------------------------------------------------------
#define GBM 128
#define GBK 32
#define SMPAD 40

__global__ __launch_bounds__(256)
void gemm_bf16_tn(const bf16* __restrict__ A, const bf16* __restrict__ B,
                  float* __restrict__ C, int M, int N, int Kb,
                  long long sA, long long sB, long long sC, int causal, int pv)
{
    const int bm = blockIdx.y * GBM;
    const int bn = blockIdx.x * GBM;
    if (causal && bn > bm + GBM - 1) return;

    A += (long long)blockIdx.z * sA;
    B += (long long)blockIdx.z * sB;
    C += (long long)blockIdx.z * sC;

    __shared__ bf16 As[2][GBM][SMPAD];
    __shared__ bf16 Bs[2][GBM][SMPAD];

    const int tid  = threadIdx.x;
    const int lane = tid & 31;
    const int wid  = tid >> 5;
    const int wm   = (wid >> 2) * 64;
    const int wn   = (wid & 3) * 32;
    const int gid  = lane >> 2;
    const int tig  = lane & 3;

    const int lr = tid >> 2;            // 0..63
    const int lc = (tid & 3) * 8;       // 0,8,16,24

    float acc[4][4][4];
#pragma unroll
    for (int a = 0; a < 4; a++)
#pragma unroll
        for (int b = 0; b < 4; b++)
#pragma unroll
            for (int c = 0; c < 4; c++) acc[a][b][c] = 0.f;

    const int rowlen = 2 * Kb;
    const int tps_full = Kb / GBK;
    int per_seg = tps_full;
    if (pv) {
        per_seg = bm / GBK + 4;
        if (per_seg > tps_full) per_seg = tps_full;
    }
    const int ntiles = 3 * per_seg;

    const bool aval = (bm + lr) < M;
    const bool bval = (bn + lr) < N;

    uint4 av0, av1, bv0, bv1;
    auto glob_load = [&](int i) {
        const int seg = i / per_seg;
        const int w   = i - seg * per_seg;
        const int kA  = ((seg == 1) ? Kb : 0) + w * GBK;   // A map {0,1,0}
        const int kB  = ((seg == 2) ? Kb : 0) + w * GBK;   // B map {0,0,1}
        const bf16* Ap = A + (size_t)(bm + lr) * rowlen + kA + lc;
        av0 = aval ? *(const uint4*)Ap                         : make_uint4(0,0,0,0);
        av1 = aval ? *(const uint4*)(Ap + (size_t)64 * rowlen) : make_uint4(0,0,0,0);
        const int n0 = bn + lr;
        const bf16* Bp = B + (size_t)n0 * rowlen + kB + lc;
        bv0 = (n0      < N) ? *(const uint4*)Bp                         : make_uint4(0,0,0,0);
        bv1 = (n0 + 64 < N) ? *(const uint4*)(Bp + (size_t)64 * rowlen) : make_uint4(0,0,0,0);
    };
    auto sts = [&](int buf) {
        *(uint4*)&As[buf][lr     ][lc] = av0;
        *(uint4*)&As[buf][lr + 64][lc] = av1;
        *(uint4*)&Bs[buf][lr     ][lc] = bv0;
        *(uint4*)&Bs[buf][lr + 64][lc] = bv1;
    };

    const uint32_t as_base = smem_u32(&As[0][0][0]);
    const uint32_t bs_base = smem_u32(&Bs[0][0][0]);
    const uint32_t BUFB = GBM * SMPAD * 2;

    const int a_row = wm + (lane & 15);
    const int a_col = (lane >> 4) * 8;
    const int b_row = wn + (lane & 7);
    const int b_col = ((lane >> 3) & 1) * 8;

    auto compute = [&](int buf) {
#pragma unroll
        for (int ks = 0; ks < 2; ks++) {
            uint32_t af[4][4], bfr[4][2];
#pragma unroll
            for (int mt = 0; mt < 4; mt++) {
                uint32_t addr = as_base + buf * BUFB +
                    (uint32_t)(((a_row + mt * 16) * SMPAD + ks * 16 + a_col) * 2);
                ldsm_x4(af[mt][0], af[mt][1], af[mt][2], af[mt][3], addr);
            }
#pragma unroll
            for (int nt = 0; nt < 4; nt++) {
                uint32_t addr = bs_base + buf * BUFB +
                    (uint32_t)(((b_row + nt * 8) * SMPAD + ks * 16 + b_col) * 2);
                ldsm_x2(bfr[nt][0], bfr[nt][1], addr);
            }
#pragma unroll
            for (int mt = 0; mt < 4; mt++)
#pragma unroll
                for (int nt = 0; nt < 4; nt++)
                    mma16816(acc[mt][nt], af[mt], bfr[nt]);
        }
    };

    glob_load(0);
    sts(0);
    __syncthreads();
    int buf = 0;
    for (int kt = 0; kt < ntiles; kt++) {
        if (kt + 1 < ntiles) glob_load(kt + 1);
        compute(buf);
        if (kt + 1 < ntiles) {
            sts(buf ^ 1);
            __syncthreads();
            buf ^= 1;
        }
    }

#pragma unroll
    for (int mt = 0; mt < 4; mt++) {
        const int row = bm + wm + mt * 16 + gid;
        if (row < M) {
#pragma unroll
            for (int nt = 0; nt < 4; nt++) {
                const int col = bn + wn + nt * 8 + tig * 2;
                if (col < N) {
                    *(float2*)&C[(size_t)row * N + col] =
                        make_float2(acc[mt][nt][0], acc[mt][nt][1]);
                    *(float2*)&C[(size_t)(row + 8) * N + col] =
                        make_float2(acc[mt][nt][2], acc[mt][nt][3]);
                }
            }
        }
    }
}

// ---------------------------------------------------------------------------
// fp32 -> bf16 split-2 ([hi|lo]), one row per block, vectorized.
// C must be a multiple of 4.
// ---------------------------------------------------------------------------
__global__ __launch_bounds__(256)
void split2_rows(const float* __restrict__ x, bf16* __restrict__ y, int C)
{
    const int row = blockIdx.x;
    const float* xr = x + (size_t)row * C;
    bf16* yr = y + (size_t)row * 2 * C;
    for (int j = threadIdx.x * 4; j < C; j += 256 * 4) {
        float4 v = *(const float4*)&xr[j];
        bf16 h0, l0, h1, l1, h2, l2, h3, l3;
        split2(v.x, h0, l0); split2(v.y, h1, l1);
        split2(v.z, h2, l2); split2(v.w, h3, l3);
        __nv_bfloat162 hh01, hh23, ll01, ll23;
        hh01.x = h0; hh01.y = h1; hh23.x = h2; hh23.y = h3;
        ll01.x = l0; ll01.y = l1; ll23.x = l2; ll23.y = l3;
        *(__nv_bfloat162*)&yr[j]         = hh01;
        *(__nv_bfloat162*)&yr[j + 2]     = hh23;
        *(__nv_bfloat162*)&yr[C + j]     = ll01;
        *(__nv_bfloat162*)&yr[C + j + 2] = ll23;
    }
}

// ---------------------------------------------------------------------------
// RMSNorm fused with split-2 output
// ---------------------------------------------------------------------------
__global__ __launch_bounds__(256)
void rmsnorm_split(const float* __restrict__ x, const float* __restrict__ w,
                   bf16* __restrict__ y2, int len, int xstride)
{
    const int row = blockIdx.x;
    const float* xr = x + (size_t)row * xstride;
    bf16* yr = y2 + (size_t)row * 2 * len;

    float ss = 0.f;
    for (int j = threadIdx.x; j < len; j += 256) { float v = xr[j]; ss += v * v; }
    __shared__ float red[256];
    red[threadIdx.x] = ss;
    __syncthreads();
    for (int s = 128; s > 0; s >>= 1) {
        if (threadIdx.x < s) red[threadIdx.x] += red[threadIdx.x + s];
        __syncthreads();
    }
    const float inv = rsqrtf(red[0] / (float)len + RMS_EPS);
    for (int j = threadIdx.x; j < len; j += 256) {
        bf16 h, l;
        split2(w[j] * xr[j] * inv, h, l);
        yr[j] = h; yr[len + j] = l;
    }
}

// ---------------------------------------------------------------------------
// RoPE helper
// ---------------------------------------------------------------------------
__device__ __forceinline__ void rope_cs(int pos, int jj, float& c, float& s)
{
    int i = jj & 31;
    float inv = __expf(-((float)(2 * i) / (float)QK_ROPE) * logf(ROPE_BASE));
    float ang = (float)pos * inv;
    c = cosf(ang);
    s = sinf(ang);
}

__global__ void assemble_q(float scale)
{
    const int s = blockIdx.x, h = blockIdx.y, j = threadIdx.x;
    const float* src = g_qfull + (size_t)s * QB_OUT + h * Q_HEAD;
    float v = src[j];
    if (j >= QK_NOPE) {
        int jj = j - QK_NOPE;
        float c, sn;
        rope_cs(s, jj, c, sn);
        float other = (jj < 32) ? -src[QK_NOPE + jj + 32] : src[QK_NOPE + jj - 32];
        v = v * c + other * sn;
    }
    v *= scale;
    bf16 hh, ll;
    split2(v, hh, ll);
    bf16* dst = g_Q2 + ((size_t)h * S_LEN + s) * 2 * Q_HEAD;
    dst[j] = hh; dst[Q_HEAD + j] = ll;
}

__global__ void assemble_k()
{
    const int s = blockIdx.x, h = blockIdx.y, j = threadIdx.x;
    float v;
    if (j < QK_NOPE) {
        v = g_kvexp[(size_t)s * KVB_OUT + h * (QK_NOPE + V_DIM) + j];
    } else {
        int jj = j - QK_NOPE;
        const float* pe = g_kv + (size_t)s * KV_IN + KV_LORA;
        float c, sn;
        rope_cs(s, jj, c, sn);
        float other = (jj < 32) ? -pe[jj + 32] : pe[jj - 32];
        v = pe[jj] * c + other * sn;
    }
    bf16 hh, ll;
    split2(v, hh, ll);
    bf16* dst = g_K2 + ((size_t)h * S_LEN + s) * 2 * Q_HEAD;
    dst[j] = hh; dst[Q_HEAD + j] = ll;
}

__global__ void assemble_vt()
{
    __shared__ float sm[32][33];
    const int h = blockIdx.z;
    const int s0 = blockIdx.x * 32, d0 = blockIdx.y * 32;
    const int tx = threadIdx.x, ty = threadIdx.y;
    sm[ty][tx] = g_kvexp[(size_t)(s0 + ty) * KVB_OUT +
                         h * (QK_NOPE + V_DIM) + QK_NOPE + d0 + tx];
    __syncthreads();
    const int d = d0 + ty, s = s0 + tx;
    bf16 hh, ll;
    split2(sm[tx][ty], hh, ll);
    bf16* dst = g_Vt2 + ((size_t)h * V_DIM + d) * 2 * S_LEN;
    dst[s] = hh; dst[S_LEN + s] = ll;
}

// ---------------------------------------------------------------------------
// Causal softmax: fp32 scores -> split-2 P.
// ---------------------------------------------------------------------------
__global__ __launch_bounds__(256)
void softmax_split()
{
    const int q = blockIdx.x, h = blockIdx.y;
    const float* row = g_scores + ((size_t)h * S_LEN + q) * S_LEN;
    bf16* prow = g_P2 + ((size_t)h * S_LEN + q) * 2 * S_LEN;
    const int L = q + 1;

    __shared__ float red[256];

    float m = -1e30f;
    for (int j = threadIdx.x; j < L; j += 256) m = fmaxf(m, row[j]);
    red[threadIdx.x] = m;
    __syncthreads();
    for (int s = 128; s > 0; s >>= 1) {
        if (threadIdx.x < s)
            red[threadIdx.x] = fmaxf(red[threadIdx.x], red[threadIdx.x + s]);
        __syncthreads();
    }
    m = red[0];
    __syncthreads();

    float ev[8];
    int cnt = 0;
    float sum = 0.f;
    for (int j = threadIdx.x; j < L; j += 256) {
        float e = __expf(row[j] - m);
        ev[cnt++] = e;
        sum += e;
    }
    red[threadIdx.x] = sum;
    __syncthreads();
    for (int s = 128; s > 0; s >>= 1) {
        if (threadIdx.x < s) red[threadIdx.x] += red[threadIdx.x + s];
        __syncthreads();
    }
    const float invs = 1.f / red[0];

    cnt = 0;
    for (int j = threadIdx.x; j < L; j += 256) {
        bf16 hh, ll;
        split2(ev[cnt++] * invs, hh, ll);
        prow[j] = hh; prow[S_LEN + j] = ll;
    }
    const int kz = ((q >> 7) << 7) + 128;   // PV k-tile skip reads no further
    bf16 z = __float2bfloat16(0.f);
    for (int j = L + threadIdx.x; j < kz; j += 256) {
        prow[j] = z; prow[S_LEN + j] = z;
    }
}

__global__ void transpose_attn_split()
{
    const int s = blockIdx.x, h = blockIdx.y, d = threadIdx.x;
    float v = g_O[((size_t)h * S_LEN + s) * V_DIM + d];
    bf16 hh, ll;
    split2(v, hh, ll);
    bf16* dst = g_attn2 + (size_t)s * 2 * (NH * V_DIM);
    const int c = h * V_DIM + d;
    dst[c] = hh;
    dst[NH * V_DIM + c] = ll;
}

// ---------------------------------------------------------------------------
// Host launch
// ---------------------------------------------------------------------------
extern "C" void kernel_launch(void* const* d_in, const int* in_sizes, int n_in,
                              void* d_out, int out_size)
{
    (void)in_sizes; (void)n_in; (void)out_size;
    const float* hidden = (const float*)d_in[0];
    const float* wq_a   = (const float*)d_in[2];
    const float* qnw    = (const float*)d_in[3];
    const float* wq_b   = (const float*)d_in[4];
    const float* wkv_a  = (const float*)d_in[5];
    const float* kvnw   = (const float*)d_in[6];
    const float* wkv_b  = (const float*)d_in[7];
    const float* wo     = (const float*)d_in[8];
    float* out = (float*)d_out;

    float *qlat_raw, *kv, *qfull, *kvexp, *scores, *O;
    bf16 *hidden2, *wqa2, *wkva2, *qlat2, *wqb2, *ckv2, *wkvb2;
    bf16 *Q2, *K2, *Vt2, *P2, *attn2, *wo2;
    cudaGetSymbolAddress((void**)&qlat_raw, g_qlat_raw);
    cudaGetSymbolAddress((void**)&kv,       g_kv);
    cudaGetSymbolAddress((void**)&qfull,    g_qfull);
    cudaGetSymbolAddress((void**)&kvexp,    g_kvexp);
    cudaGetSymbolAddress((void**)&scores,   g_scores);
    cudaGetSymbolAddress((void**)&O,        g_O);
    cudaGetSymbolAddress((void**)&hidden2,  g_hidden2);
    cudaGetSymbolAddress((void**)&wqa2,     g_wqa2);
    cudaGetSymbolAddress((void**)&wkva2,    g_wkva2);
    cudaGetSymbolAddress((void**)&qlat2,    g_qlat2);
    cudaGetSymbolAddress((void**)&wqb2,     g_wqb2);
    cudaGetSymbolAddress((void**)&ckv2,     g_ckv2);
    cudaGetSymbolAddress((void**)&wkvb2,    g_wkvb2);
    cudaGetSymbolAddress((void**)&Q2,       g_Q2);
    cudaGetSymbolAddress((void**)&K2,       g_K2);
    cudaGetSymbolAddress((void**)&Vt2,      g_Vt2);
    cudaGetSymbolAddress((void**)&P2,       g_P2);
    cudaGetSymbolAddress((void**)&attn2,    g_attn2);
    cudaGetSymbolAddress((void**)&wo2,      g_wo2);

    const float softmax_scale = rsqrtf((float)Q_HEAD);
    dim3 blk(256);

    // split-2 of inputs / weights (one row per block)
    split2_rows<<<S_LEN,   256>>>(hidden, hidden2, HID);
    split2_rows<<<Q_LORA,  256>>>(wq_a,  wqa2,  HID);
    split2_rows<<<KV_IN,   256>>>(wkv_a, wkva2, HID);
    split2_rows<<<QB_OUT,  256>>>(wq_b,  wqb2,  Q_LORA);
    split2_rows<<<KVB_OUT, 256>>>(wkv_b, wkvb2, KV_LORA);
    split2_rows<<<HID,     256>>>(wo,    wo2,   NH * V_DIM);

    // 1. q_lat_raw = hidden @ wq_a^T
    gemm_bf16_tn<<<dim3(Q_LORA / 128, S_LEN / 128, 1), blk>>>(
        hidden2, wqa2, qlat_raw, S_LEN, Q_LORA, HID, 0, 0, 0, 0, 0);
    // 2. kv = hidden @ wkv_a^T  (N=576, guarded)
    gemm_bf16_tn<<<dim3((KV_IN + 127) / 128, S_LEN / 128, 1), blk>>>(
        hidden2, wkva2, kv, S_LEN, KV_IN, HID, 0, 0, 0, 0, 0);
    // 3-4. RMSNorms with fused split
    rmsnorm_split<<<S_LEN, 256>>>(qlat_raw, qnw, qlat2, Q_LORA, Q_LORA);
    rmsnorm_split<<<S_LEN, 256>>>(kv, kvnw, ckv2, KV_LORA, KV_IN);
    // 5. q = q_lat @ wq_b^T
    gemm_bf16_tn<<<dim3(QB_OUT / 128, S_LEN / 128, 1), blk>>>(
        qlat2, wqb2, qfull, S_LEN, QB_OUT, Q_LORA, 0, 0, 0, 0, 0);
    // 6. kv_exp = ckv @ wkv_b^T
    gemm_bf16_tn<<<dim3(KVB_OUT / 128, S_LEN / 128, 1), blk>>>(
        ckv2, wkvb2, kvexp, S_LEN, KVB_OUT, KV_LORA, 0, 0, 0, 0, 0);
    // 7-9. assemble split operands
    assemble_q<<<dim3(S_LEN, NH), Q_HEAD>>>(softmax_scale);
    assemble_k<<<dim3(S_LEN, NH), Q_HEAD>>>();
    assemble_vt<<<dim3(S_LEN / 32, V_DIM / 32, NH), dim3(32, 32)>>>();
    // 10. scores = Q @ K^T (causal blocks skipped)
    gemm_bf16_tn<<<dim3(S_LEN / 128, S_LEN / 128, NH), blk>>>(
        Q2, K2, scores, S_LEN, S_LEN, Q_HEAD,
        (long long)S_LEN * 2 * Q_HEAD, (long long)S_LEN * 2 * Q_HEAD,
        (long long)S_LEN * S_LEN, 1, 0);
    // 11. causal softmax + split
    softmax_split<<<dim3(S_LEN, NH), 256>>>();
    // 12. O = P @ V (causal k-tile skip)
    gemm_bf16_tn<<<dim3(1, S_LEN / 128, NH), blk>>>(
        P2, Vt2, O, S_LEN, V_DIM, S_LEN,
        (long long)S_LEN * 2 * S_LEN, (long long)V_DIM * 2 * S_LEN,
        (long long)S_LEN * V_DIM, 0, 1);
    // 13. flatten heads + split
    transpose_attn_split<<<dim3(S_LEN, NH), V_DIM>>>();
    // 14. out = attn @ wo^T
    gemm_bf16_tn<<<dim3(HID / 128, S_LEN / 128, 1), blk>>>(
        attn2, wo2, out, S_LEN, HID, NH * V_DIM, 0, 0, 0, 0, 0);
}

// round 7
// speedup vs baseline: 1.2436x; 1.0637x over previous
#include <cuda_runtime.h>
#include <cuda_bf16.h>
#include <math.h>
#include <stdint.h>

// ---------------------------------------------------------------------------
// Problem constants
// ---------------------------------------------------------------------------
#define S_LEN   2048
#define HID     4096
#define Q_LORA  1536
#define KV_LORA 512
#define KV_IN   576
#define NH      16
#define QK_NOPE 128
#define QK_ROPE 64
#define Q_HEAD  192
#define V_DIM   128
#define QB_OUT  (NH * Q_HEAD)            // 3072
#define KVB_OUT (NH * (QK_NOPE + V_DIM)) // 4096
#define RMS_EPS 1e-6f
#define ROPE_BASE 10000.0f

typedef __nv_bfloat16 bf16;

// ---------------------------------------------------------------------------
// Static device scratch (split-2 [hi|lo] storage; GEMMs do 3 logical segment
// products with maps A:{0,1,0}, B:{0,0,1})
// ---------------------------------------------------------------------------
__device__ float g_qlat_raw[S_LEN * Q_LORA];
__device__ float g_kv      [S_LEN * KV_IN];
__device__ float g_qfull   [S_LEN * QB_OUT];
__device__ float g_kvexp   [S_LEN * KVB_OUT];

__device__ bf16 g_hidden2 [(size_t)S_LEN * 2 * HID];
__device__ bf16 g_wqa2    [(size_t)Q_LORA * 2 * HID];
__device__ bf16 g_wkva2   [(size_t)KV_IN * 2 * HID];
__device__ bf16 g_qlat2   [(size_t)S_LEN * 2 * Q_LORA];
__device__ bf16 g_wqb2    [(size_t)QB_OUT * 2 * Q_LORA];
__device__ bf16 g_ckv2    [(size_t)S_LEN * 2 * KV_LORA];
__device__ bf16 g_wkvb2   [(size_t)KVB_OUT * 2 * KV_LORA];
__device__ bf16 g_Q2      [(size_t)NH * S_LEN * 2 * Q_HEAD];
__device__ bf16 g_K2      [(size_t)NH * S_LEN * 2 * Q_HEAD];
__device__ bf16 g_Vt2     [(size_t)NH * V_DIM * 2 * S_LEN];
__device__ bf16 g_attn2   [(size_t)S_LEN * 2 * (NH * V_DIM)];
__device__ bf16 g_wo2     [(size_t)HID * 2 * (NH * V_DIM)];

// ---------------------------------------------------------------------------
// helpers
// ---------------------------------------------------------------------------
__device__ __forceinline__ uint32_t smem_u32(const void* p) {
    return (uint32_t)__cvta_generic_to_shared(p);
}
__device__ __forceinline__ void ldsm_x4(uint32_t& r0, uint32_t& r1,
                                        uint32_t& r2, uint32_t& r3, uint32_t addr) {
    asm volatile("ldmatrix.sync.aligned.m8n8.x4.shared.b16 {%0,%1,%2,%3}, [%4];"
                 : "=r"(r0), "=r"(r1), "=r"(r2), "=r"(r3) : "r"(addr));
}
__device__ __forceinline__ void ldsm_x2(uint32_t& r0, uint32_t& r1, uint32_t addr) {
    asm volatile("ldmatrix.sync.aligned.m8n8.x2.shared.b16 {%0,%1}, [%2];"
                 : "=r"(r0), "=r"(r1) : "r"(addr));
}
__device__ __forceinline__ void mma16816(float* c, const uint32_t* a, const uint32_t* b) {
    asm volatile("mma.sync.aligned.m16n8k16.row.col.f32.bf16.bf16.f32 "
                 "{%0,%1,%2,%3}, {%4,%5,%6,%7}, {%8,%9}, {%0,%1,%2,%3};"
                 : "+f"(c[0]), "+f"(c[1]), "+f"(c[2]), "+f"(c[3])
                 : "r"(a[0]), "r"(a[1]), "r"(a[2]), "r"(a[3]),
                   "r"(b[0]), "r"(b[1]));
}
__device__ __forceinline__ void split2(float v, bf16& h, bf16& l) {
    h = __float2bfloat16(v);
    l = __float2bfloat16(v - __bfloat162float(h));
}

// ---------------------------------------------------------------------------
// Dense bf16 TN GEMM (proven core): split-2 storage + 3 logical products.
// ---------------------------------------------------------------------------
#define GBM 128
#define GBK 32
#define SMPAD 40

__global__ __launch_bounds__(256)
void gemm_bf16_tn(const bf16* __restrict__ A, const bf16* __restrict__ B,
                  float* __restrict__ C, int M, int N, int Kb)
{
    const int bm = blockIdx.y * GBM;
    const int bn = blockIdx.x * GBM;

    __shared__ bf16 As[2][GBM][SMPAD];
    __shared__ bf16 Bs[2][GBM][SMPAD];

    const int tid  = threadIdx.x;
    const int lane = tid & 31;
    const int wid  = tid >> 5;
    const int wm   = (wid >> 2) * 64;
    const int wn   = (wid & 3) * 32;
    const int gid  = lane >> 2;
    const int tig  = lane & 3;

    const int lr = tid >> 2;
    const int lc = (tid & 3) * 8;

    float acc[4][4][4];
#pragma unroll
    for (int a = 0; a < 4; a++)
#pragma unroll
        for (int b = 0; b < 4; b++)
#pragma unroll
            for (int c = 0; c < 4; c++) acc[a][b][c] = 0.f;

    const int rowlen = 2 * Kb;
    const int per_seg = Kb / GBK;
    const int ntiles = 3 * per_seg;

    const bool aval = (bm + lr) < M;

    uint4 av0, av1, bv0, bv1;
    auto glob_load = [&](int i) {
        const int seg = i / per_seg;
        const int w   = i - seg * per_seg;
        const int kA  = ((seg == 1) ? Kb : 0) + w * GBK;
        const int kB  = ((seg == 2) ? Kb : 0) + w * GBK;
        const bf16* Ap = A + (size_t)(bm + lr) * rowlen + kA + lc;
        av0 = aval ? *(const uint4*)Ap                         : make_uint4(0,0,0,0);
        av1 = aval ? *(const uint4*)(Ap + (size_t)64 * rowlen) : make_uint4(0,0,0,0);
        const int n0 = bn + lr;
        const bf16* Bp = B + (size_t)n0 * rowlen + kB + lc;
        bv0 = (n0      < N) ? *(const uint4*)Bp                         : make_uint4(0,0,0,0);
        bv1 = (n0 + 64 < N) ? *(const uint4*)(Bp + (size_t)64 * rowlen) : make_uint4(0,0,0,0);
    };
    auto sts = [&](int buf) {
        *(uint4*)&As[buf][lr     ][lc] = av0;
        *(uint4*)&As[buf][lr + 64][lc] = av1;
        *(uint4*)&Bs[buf][lr     ][lc] = bv0;
        *(uint4*)&Bs[buf][lr + 64][lc] = bv1;
    };

    const uint32_t as_base = smem_u32(&As[0][0][0]);
    const uint32_t bs_base = smem_u32(&Bs[0][0][0]);
    const uint32_t BUFB = GBM * SMPAD * 2;

    const int a_row = wm + (lane & 15);
    const int a_col = (lane >> 4) * 8;
    const int b_row = wn + (lane & 7);
    const int b_col = ((lane >> 3) & 1) * 8;

    auto compute = [&](int buf) {
#pragma unroll
        for (int ks = 0; ks < 2; ks++) {
            uint32_t af[4][4], bfr[4][2];
#pragma unroll
            for (int mt = 0; mt < 4; mt++) {
                uint32_t addr = as_base + buf * BUFB +
                    (uint32_t)(((a_row + mt * 16) * SMPAD + ks * 16 + a_col) * 2);
                ldsm_x4(af[mt][0], af[mt][1], af[mt][2], af[mt][3], addr);
            }
#pragma unroll
            for (int nt = 0; nt < 4; nt++) {
                uint32_t addr = bs_base + buf * BUFB +
                    (uint32_t)(((b_row + nt * 8) * SMPAD + ks * 16 + b_col) * 2);
                ldsm_x2(bfr[nt][0], bfr[nt][1], addr);
            }
#pragma unroll
            for (int mt = 0; mt < 4; mt++)
#pragma unroll
                for (int nt = 0; nt < 4; nt++)
                    mma16816(acc[mt][nt], af[mt], bfr[nt]);
        }
    };

    glob_load(0);
    sts(0);
    __syncthreads();
    int buf = 0;
    for (int kt = 0; kt < ntiles; kt++) {
        if (kt + 1 < ntiles) glob_load(kt + 1);
        compute(buf);
        if (kt + 1 < ntiles) {
            sts(buf ^ 1);
            __syncthreads();
            buf ^= 1;
        }
    }

#pragma unroll
    for (int mt = 0; mt < 4; mt++) {
        const int row = bm + wm + mt * 16 + gid;
        if (row < M) {
#pragma unroll
            for (int nt = 0; nt < 4; nt++) {
                const int col = bn + wn + nt * 8 + tig * 2;
                if (col < N) {
                    *(float2*)&C[(size_t)row * N + col] =
                        make_float2(acc[mt][nt][0], acc[mt][nt][1]);
                    *(float2*)&C[(size_t)(row + 8) * N + col] =
                        make_float2(acc[mt][nt][2], acc[mt][nt][3]);
                }
            }
        }
    }
}

// ---------------------------------------------------------------------------
// Fused flash attention (split-2 operands, online softmax).
// Grid (8, NH): each CTA processes q-tiles qb=blockIdx.x and 15-blockIdx.x
// (uniform 17 k-block iterations). Writes g_attn2 directly (split-2).
// ---------------------------------------------------------------------------
#define FL_AS   0
#define FL_BS   20480
#define FL_PS   40960                    // Ps: 128 x 264 halves (hi|lo + pad)
#define FL_WMAX 108544                   // float[4][128]
#define FL_WSUM 110592                   // float[4][128]
#define FL_RM   112640
#define FL_RL   113152
#define FL_RC   113664
#define FL_SMEM 114176
#define PS_LDA  264

__global__ __launch_bounds__(256)
void flash_attn()
{
    extern __shared__ char sm[];
    const uint32_t sb = smem_u32(sm);
    float* wmax  = (float*)(sm + FL_WMAX);
    float* wsum  = (float*)(sm + FL_WSUM);
    float* row_m = (float*)(sm + FL_RM);
    float* row_l = (float*)(sm + FL_RL);
    float* row_c = (float*)(sm + FL_RC);
    bf16*  Ps    = (bf16*)(sm + FL_PS);

    const int h    = blockIdx.y;
    const int tid  = threadIdx.x;
    const int lane = tid & 31;
    const int wid  = tid >> 5;
    const int wm   = (wid >> 2) * 64;
    const int wn   = (wid & 3) * 32;
    const int gid  = lane >> 2;
    const int tig  = lane & 3;
    const int lr   = tid >> 2;
    const int lc   = (tid & 3) * 8;
    const int wq   = wid & 3;

    const bf16* Qh = g_Q2 + (size_t)h * S_LEN * (2 * Q_HEAD);
    const bf16* Kh = g_K2 + (size_t)h * S_LEN * (2 * Q_HEAD);
    const bf16* Vh = g_Vt2 + (size_t)h * V_DIM * (2 * S_LEN);

    const int a_row = wm + (lane & 15);
    const int a_col = (lane >> 4) * 8;
    const int b_row = wn + (lane & 7);
    const int b_col = ((lane >> 3) & 1) * 8;
    const uint32_t BUFB = 128 * SMPAD * 2;

    for (int half = 0; half < 2; half++) {
        const int qb = half ? (15 - (int)blockIdx.x) : (int)blockIdx.x;
        const int q0 = qb * 128;

        if (tid < 128) { row_m[tid] = -1e30f; row_l[tid] = 0.f; }
        float acc_o[4][4][4];
#pragma unroll
        for (int a = 0; a < 4; a++)
#pragma unroll
            for (int b = 0; b < 4; b++)
#pragma unroll
                for (int c = 0; c < 4; c++) acc_o[a][b][c] = 0.f;
        __syncthreads();

        for (int jb = 0; jb <= qb; jb++) {
            // ================= S = Q K^T (18 k-tiles, segment remap) =======
            float acc_s[4][4][4];
#pragma unroll
            for (int a = 0; a < 4; a++)
#pragma unroll
                for (int b = 0; b < 4; b++)
#pragma unroll
                    for (int c = 0; c < 4; c++) acc_s[a][b][c] = 0.f;

            uint4 av0, av1, bv0, bv1;
            auto gload = [&](int i) {
                const int seg = i / 6, w = i - seg * 6;
                const int kA = ((seg == 1) ? Q_HEAD : 0) + w * 32;
                const int kB = ((seg == 2) ? Q_HEAD : 0) + w * 32;
                const bf16* Ap = Qh + (size_t)(q0 + lr) * 384 + kA + lc;
                const bf16* Bp = Kh + (size_t)(jb * 128 + lr) * 384 + kB + lc;
                av0 = *(const uint4*)Ap;
                av1 = *(const uint4*)(Ap + (size_t)64 * 384);
                bv0 = *(const uint4*)Bp;
                bv1 = *(const uint4*)(Bp + (size_t)64 * 384);
            };
            auto sts = [&](int buf) {
                *(uint4*)(sm + FL_AS + buf * BUFB + (uint32_t)((lr * SMPAD + lc) * 2))        = av0;
                *(uint4*)(sm + FL_AS + buf * BUFB + (uint32_t)(((lr + 64) * SMPAD + lc) * 2)) = av1;
                *(uint4*)(sm + FL_BS + buf * BUFB + (uint32_t)((lr * SMPAD + lc) * 2))        = bv0;
                *(uint4*)(sm + FL_BS + buf * BUFB + (uint32_t)(((lr + 64) * SMPAD + lc) * 2)) = bv1;
            };
            auto computeS = [&](int buf) {
#pragma unroll
                for (int ks = 0; ks < 2; ks++) {
                    uint32_t af[4][4], bfr[4][2];
#pragma unroll
                    for (int mt = 0; mt < 4; mt++) {
                        uint32_t addr = sb + FL_AS + buf * BUFB +
                            (uint32_t)(((a_row + mt * 16) * SMPAD + ks * 16 + a_col) * 2);
                        ldsm_x4(af[mt][0], af[mt][1], af[mt][2], af[mt][3], addr);
                    }
#pragma unroll
                    for (int nt = 0; nt < 4; nt++) {
                        uint32_t addr = sb + FL_BS + buf * BUFB +
                            (uint32_t)(((b_row + nt * 8) * SMPAD + ks * 16 + b_col) * 2);
                        ldsm_x2(bfr[nt][0], bfr[nt][1], addr);
                    }
#pragma unroll
                    for (int mt = 0; mt < 4; mt++)
#pragma unroll
                        for (int nt = 0; nt < 4; nt++)
                            mma16816(acc_s[mt][nt], af[mt], bfr[nt]);
                }
            };

            gload(0); sts(0); __syncthreads();
            int buf = 0;
            for (int kt = 0; kt < 18; kt++) {
                if (kt + 1 < 18) gload(kt + 1);
                computeS(buf);
                if (kt + 1 < 18) { sts(buf ^ 1); __syncthreads(); buf ^= 1; }
            }

            // ================= mask (diagonal block) ========================
            if (jb == qb) {
#pragma unroll
                for (int mt = 0; mt < 4; mt++) {
                    const int m0 = wm + mt * 16 + gid;
#pragma unroll
                    for (int nt = 0; nt < 4; nt++) {
                        const int n0 = wn + nt * 8 + tig * 2;
                        if (n0     > m0    ) acc_s[mt][nt][0] = -1e30f;
                        if (n0 + 1 > m0    ) acc_s[mt][nt][1] = -1e30f;
                        if (n0     > m0 + 8) acc_s[mt][nt][2] = -1e30f;
                        if (n0 + 1 > m0 + 8) acc_s[mt][nt][3] = -1e30f;
                    }
                }
            }
            __syncthreads();   // S compute fully done; wmax/wsum free

            // ================= row max (warp + cross-warp) ==================
            float rmx[4][2];
#pragma unroll
            for (int mt = 0; mt < 4; mt++) {
                float m0 = -1e30f, m1 = -1e30f;
#pragma unroll
                for (int nt = 0; nt < 4; nt++) {
                    m0 = fmaxf(m0, fmaxf(acc_s[mt][nt][0], acc_s[mt][nt][1]));
                    m1 = fmaxf(m1, fmaxf(acc_s[mt][nt][2], acc_s[mt][nt][3]));
                }
                rmx[mt][0] = m0; rmx[mt][1] = m1;
            }
#pragma unroll
            for (int o = 1; o < 4; o <<= 1)
#pragma unroll
                for (int mt = 0; mt < 4; mt++) {
                    rmx[mt][0] = fmaxf(rmx[mt][0], __shfl_xor_sync(0xffffffffu, rmx[mt][0], o));
                    rmx[mt][1] = fmaxf(rmx[mt][1], __shfl_xor_sync(0xffffffffu, rmx[mt][1], o));
                }
            if (tig == 0) {
#pragma unroll
                for (int mt = 0; mt < 4; mt++) {
                    wmax[wq * 128 + wm + mt * 16 + gid]     = rmx[mt][0];
                    wmax[wq * 128 + wm + mt * 16 + gid + 8] = rmx[mt][1];
                }
            }
            __syncthreads();

            // ========== P = exp(S-new_m), write Ps (hi|lo), partial sums ====
            float psum[4][2];
#pragma unroll
            for (int mt = 0; mt < 4; mt++) {
#pragma unroll
                for (int rr = 0; rr < 2; rr++) {
                    const int r = wm + mt * 16 + gid + rr * 8;
                    float bmx = fmaxf(fmaxf(wmax[r], wmax[128 + r]),
                                      fmaxf(wmax[256 + r], wmax[384 + r]));
                    const float newm = fmaxf(row_m[r], bmx);
                    float s = 0.f;
#pragma unroll
                    for (int nt = 0; nt < 4; nt++) {
                        const int n0 = wn + nt * 8 + tig * 2;
                        float p0 = __expf(acc_s[mt][nt][rr * 2 + 0] - newm);
                        float p1 = __expf(acc_s[mt][nt][rr * 2 + 1] - newm);
                        s += p0 + p1;
                        bf16 h0, l0, h1, l1;
                        split2(p0, h0, l0); split2(p1, h1, l1);
                        __nv_bfloat162 hp, lp;
                        hp.x = h0; hp.y = h1; lp.x = l0; lp.y = l1;
                        *(__nv_bfloat162*)&Ps[r * PS_LDA + n0]       = hp;
                        *(__nv_bfloat162*)&Ps[r * PS_LDA + 128 + n0] = lp;
                    }
                    psum[mt][rr] = s;
                }
            }
#pragma unroll
            for (int o = 1; o < 4; o <<= 1)
#pragma unroll
                for (int mt = 0; mt < 4; mt++) {
                    psum[mt][0] += __shfl_xor_sync(0xffffffffu, psum[mt][0], o);
                    psum[mt][1] += __shfl_xor_sync(0xffffffffu, psum[mt][1], o);
                }
            if (tig == 0) {
#pragma unroll
                for (int mt = 0; mt < 4; mt++) {
                    wsum[wq * 128 + wm + mt * 16 + gid]     = psum[mt][0];
                    wsum[wq * 128 + wm + mt * 16 + gid + 8] = psum[mt][1];
                }
            }
            __syncthreads();

            // ================= per-row state update ========================
            if (tid < 128) {
                const int r = tid;
                float bmx = fmaxf(fmaxf(wmax[r], wmax[128 + r]),
                                  fmaxf(wmax[256 + r], wmax[384 + r]));
                const float old  = row_m[r];
                const float newm = fmaxf(old, bmx);
                const float corr = __expf(old - newm);
                const float bs = wsum[r] + wsum[128 + r] + wsum[256 + r] + wsum[384 + r];
                row_l[r] = row_l[r] * corr + bs;
                row_m[r] = newm;
                row_c[r] = corr;
            }
            __syncthreads();

            // rescale O accumulator
#pragma unroll
            for (int mt = 0; mt < 4; mt++) {
                const float c0 = row_c[wm + mt * 16 + gid];
                const float c1 = row_c[wm + mt * 16 + gid + 8];
#pragma unroll
                for (int nt = 0; nt < 4; nt++) {
                    acc_o[mt][nt][0] *= c0; acc_o[mt][nt][1] *= c0;
                    acc_o[mt][nt][2] *= c1; acc_o[mt][nt][3] *= c1;
                }
            }

            // ================= O += P V  (12 k-tiles) ========================
            auto gloadV = [&](int t) {
                const int seg = t >> 2, w = t & 3;
                const int kB = ((seg == 2) ? S_LEN : 0) + jb * 128 + w * 32;
                const bf16* Bp = Vh + (size_t)lr * (2 * S_LEN) + kB + lc;
                bv0 = *(const uint4*)Bp;
                bv1 = *(const uint4*)(Bp + (size_t)64 * (2 * S_LEN));
            };
            auto stsV = [&](int b2) {
                *(uint4*)(sm + FL_BS + b2 * BUFB + (uint32_t)((lr * SMPAD + lc) * 2))        = bv0;
                *(uint4*)(sm + FL_BS + b2 * BUFB + (uint32_t)(((lr + 64) * SMPAD + lc) * 2)) = bv1;
            };
            auto computePV = [&](int t, int b2) {
                const int seg = t >> 2, w = t & 3;
                const int kA = ((seg == 1) ? 128 : 0) + w * 32;
#pragma unroll
                for (int ks = 0; ks < 2; ks++) {
                    uint32_t af[4][4], bfr[4][2];
#pragma unroll
                    for (int mt = 0; mt < 4; mt++) {
                        uint32_t addr = sb + FL_PS +
                            (uint32_t)(((a_row + mt * 16) * PS_LDA + kA + ks * 16 + a_col) * 2);
                        ldsm_x4(af[mt][0], af[mt][1], af[mt][2], af[mt][3], addr);
                    }
#pragma unroll
                    for (int nt = 0; nt < 4; nt++) {
                        uint32_t addr = sb + FL_BS + b2 * BUFB +
                            (uint32_t)(((b_row + nt * 8) * SMPAD + ks * 16 + b_col) * 2);
                        ldsm_x2(bfr[nt][0], bfr[nt][1], addr);
                    }
#pragma unroll
                    for (int mt = 0; mt < 4; mt++)
#pragma unroll
                        for (int nt = 0; nt < 4; nt++)
                            mma16816(acc_o[mt][nt], af[mt], bfr[nt]);
                }
            };

            gloadV(0); stsV(0); __syncthreads();
            for (int t = 0; t < 12; t++) {
                if (t + 1 < 12) gloadV(t + 1);
                computePV(t, t & 1);
                if (t + 1 < 12) { stsV((t & 1) ^ 1); __syncthreads(); }
            }
            __syncthreads();   // protect As/Bs/Ps reuse next jb
        }

        // ================= epilogue: O / l -> attn2 (split-2) ===============
#pragma unroll
        for (int mt = 0; mt < 4; mt++) {
            const int r0 = wm + mt * 16 + gid;
            const int r1 = r0 + 8;
            const float inv0 = 1.f / row_l[r0];
            const float inv1 = 1.f / row_l[r1];
            bf16* d0 = g_attn2 + (size_t)(q0 + r0) * (2 * NH * V_DIM);
            bf16* d1 = g_attn2 + (size_t)(q0 + r1) * (2 * NH * V_DIM);
#pragma unroll
            for (int nt = 0; nt < 4; nt++) {
                const int c = h * V_DIM + wn + nt * 8 + tig * 2;
                bf16 h0, l0, h1, l1;
                split2(acc_o[mt][nt][0] * inv0, h0, l0);
                split2(acc_o[mt][nt][1] * inv0, h1, l1);
                __nv_bfloat162 hp, lp;
                hp.x = h0; hp.y = h1; lp.x = l0; lp.y = l1;
                *(__nv_bfloat162*)&d0[c]                 = hp;
                *(__nv_bfloat162*)&d0[NH * V_DIM + c]    = lp;
                split2(acc_o[mt][nt][2] * inv1, h0, l0);
                split2(acc_o[mt][nt][3] * inv1, h1, l1);
                hp.x = h0; hp.y = h1; lp.x = l0; lp.y = l1;
                *(__nv_bfloat162*)&d1[c]                 = hp;
                *(__nv_bfloat162*)&d1[NH * V_DIM + c]    = lp;
            }
        }
        __syncthreads();   // row state reuse by next half
    }
}

// ---------------------------------------------------------------------------
// fp32 -> bf16 split-2 rows
// ---------------------------------------------------------------------------
__global__ __launch_bounds__(256)
void split2_rows(const float* __restrict__ x, bf16* __restrict__ y, int C)
{
    const int row = blockIdx.x;
    const float* xr = x + (size_t)row * C;
    bf16* yr = y + (size_t)row * 2 * C;
    for (int j = threadIdx.x * 4; j < C; j += 256 * 4) {
        float4 v = *(const float4*)&xr[j];
        bf16 h0, l0, h1, l1, h2, l2, h3, l3;
        split2(v.x, h0, l0); split2(v.y, h1, l1);
        split2(v.z, h2, l2); split2(v.w, h3, l3);
        __nv_bfloat162 hh01, hh23, ll01, ll23;
        hh01.x = h0; hh01.y = h1; hh23.x = h2; hh23.y = h3;
        ll01.x = l0; ll01.y = l1; ll23.x = l2; ll23.y = l3;
        *(__nv_bfloat162*)&yr[j]         = hh01;
        *(__nv_bfloat162*)&yr[j + 2]     = hh23;
        *(__nv_bfloat162*)&yr[C + j]     = ll01;
        *(__nv_bfloat162*)&yr[C + j + 2] = ll23;
    }
}

// ---------------------------------------------------------------------------
// RMSNorm fused with split-2 output
// ---------------------------------------------------------------------------
__global__ __launch_bounds__(256)
void rmsnorm_split(const float* __restrict__ x, const float* __restrict__ w,
                   bf16* __restrict__ y2, int len, int xstride)
{
    const int row = blockIdx.x;
    const float* xr = x + (size_t)row * xstride;
    bf16* yr = y2 + (size_t)row * 2 * len;

    float ss = 0.f;
    for (int j = threadIdx.x; j < len; j += 256) { float v = xr[j]; ss += v * v; }
    __shared__ float red[256];
    red[threadIdx.x] = ss;
    __syncthreads();
    for (int s = 128; s > 0; s >>= 1) {
        if (threadIdx.x < s) red[threadIdx.x] += red[threadIdx.x + s];
        __syncthreads();
    }
    const float inv = rsqrtf(red[0] / (float)len + RMS_EPS);
    for (int j = threadIdx.x; j < len; j += 256) {
        bf16 h, l;
        split2(w[j] * xr[j] * inv, h, l);
        yr[j] = h; yr[len + j] = l;
    }
}

// ---------------------------------------------------------------------------
// RoPE + assembles
// ---------------------------------------------------------------------------
__device__ __forceinline__ void rope_cs(int pos, int jj, float& c, float& s)
{
    int i = jj & 31;
    float inv = __expf(-((float)(2 * i) / (float)QK_ROPE) * logf(ROPE_BASE));
    float ang = (float)pos * inv;
    c = cosf(ang);
    s = sinf(ang);
}

__global__ void assemble_q(float scale)
{
    const int s = blockIdx.x, h = blockIdx.y, j = threadIdx.x;
    const float* src = g_qfull + (size_t)s * QB_OUT + h * Q_HEAD;
    float v = src[j];
    if (j >= QK_NOPE) {
        int jj = j - QK_NOPE;
        float c, sn;
        rope_cs(s, jj, c, sn);
        float other = (jj < 32) ? -src[QK_NOPE + jj + 32] : src[QK_NOPE + jj - 32];
        v = v * c + other * sn;
    }
    v *= scale;
    bf16 hh, ll;
    split2(v, hh, ll);
    bf16* dst = g_Q2 + ((size_t)h * S_LEN + s) * 2 * Q_HEAD;
    dst[j] = hh; dst[Q_HEAD + j] = ll;
}

__global__ void assemble_k()
{
    const int s = blockIdx.x, h = blockIdx.y, j = threadIdx.x;
    float v;
    if (j < QK_NOPE) {
        v = g_kvexp[(size_t)s * KVB_OUT + h * (QK_NOPE + V_DIM) + j];
    } else {
        int jj = j - QK_NOPE;
        const float* pe = g_kv + (size_t)s * KV_IN + KV_LORA;
        float c, sn;
        rope_cs(s, jj, c, sn);
        float other = (jj < 32) ? -pe[jj + 32] : pe[jj - 32];
        v = pe[jj] * c + other * sn;
    }
    bf16 hh, ll;
    split2(v, hh, ll);
    bf16* dst = g_K2 + ((size_t)h * S_LEN + s) * 2 * Q_HEAD;
    dst[j] = hh; dst[Q_HEAD + j] = ll;
}

__global__ void assemble_vt()
{
    __shared__ float sm[32][33];
    const int h = blockIdx.z;
    const int s0 = blockIdx.x * 32, d0 = blockIdx.y * 32;
    const int tx = threadIdx.x, ty = threadIdx.y;
    sm[ty][tx] = g_kvexp[(size_t)(s0 + ty) * KVB_OUT +
                         h * (QK_NOPE + V_DIM) + QK_NOPE + d0 + tx];
    __syncthreads();
    const int d = d0 + ty, s = s0 + tx;
    bf16 hh, ll;
    split2(sm[tx][ty], hh, ll);
    bf16* dst = g_Vt2 + ((size_t)h * V_DIM + d) * 2 * S_LEN;
    dst[s] = hh; dst[S_LEN + s] = ll;
}

// ---------------------------------------------------------------------------
// Host launch
// ---------------------------------------------------------------------------
extern "C" void kernel_launch(void* const* d_in, const int* in_sizes, int n_in,
                              void* d_out, int out_size)
{
    (void)in_sizes; (void)n_in; (void)out_size;
    const float* hidden = (const float*)d_in[0];
    const float* wq_a   = (const float*)d_in[2];
    const float* qnw    = (const float*)d_in[3];
    const float* wq_b   = (const float*)d_in[4];
    const float* wkv_a  = (const float*)d_in[5];
    const float* kvnw   = (const float*)d_in[6];
    const float* wkv_b  = (const float*)d_in[7];
    const float* wo     = (const float*)d_in[8];
    float* out = (float*)d_out;

    float *qlat_raw, *kv, *qfull, *kvexp;
    bf16 *hidden2, *wqa2, *wkva2, *qlat2, *wqb2, *ckv2, *wkvb2, *attn2, *wo2;
    cudaGetSymbolAddress((void**)&qlat_raw, g_qlat_raw);
    cudaGetSymbolAddress((void**)&kv,       g_kv);
    cudaGetSymbolAddress((void**)&qfull,    g_qfull);
    cudaGetSymbolAddress((void**)&kvexp,    g_kvexp);
    cudaGetSymbolAddress((void**)&hidden2,  g_hidden2);
    cudaGetSymbolAddress((void**)&wqa2,     g_wqa2);
    cudaGetSymbolAddress((void**)&wkva2,    g_wkva2);
    cudaGetSymbolAddress((void**)&qlat2,    g_qlat2);
    cudaGetSymbolAddress((void**)&wqb2,     g_wqb2);
    cudaGetSymbolAddress((void**)&ckv2,     g_ckv2);
    cudaGetSymbolAddress((void**)&wkvb2,    g_wkvb2);
    cudaGetSymbolAddress((void**)&attn2,    g_attn2);
    cudaGetSymbolAddress((void**)&wo2,      g_wo2);

    const float softmax_scale = rsqrtf((float)Q_HEAD);
    dim3 blk(256);

    cudaFuncSetAttribute(flash_attn, cudaFuncAttributeMaxDynamicSharedMemorySize,
                         FL_SMEM);

    // split-2 of inputs / weights
    split2_rows<<<S_LEN,   256>>>(hidden, hidden2, HID);
    split2_rows<<<Q_LORA,  256>>>(wq_a,  wqa2,  HID);
    split2_rows<<<KV_IN,   256>>>(wkv_a, wkva2, HID);
    split2_rows<<<QB_OUT,  256>>>(wq_b,  wqb2,  Q_LORA);
    split2_rows<<<KVB_OUT, 256>>>(wkv_b, wkvb2, KV_LORA);
    split2_rows<<<HID,     256>>>(wo,    wo2,   NH * V_DIM);

    // dense GEMMs
    gemm_bf16_tn<<<dim3(Q_LORA / 128, S_LEN / 128, 1), blk>>>(
        hidden2, wqa2, qlat_raw, S_LEN, Q_LORA, HID);
    gemm_bf16_tn<<<dim3((KV_IN + 127) / 128, S_LEN / 128, 1), blk>>>(
        hidden2, wkva2, kv, S_LEN, KV_IN, HID);
    rmsnorm_split<<<S_LEN, 256>>>(qlat_raw, qnw, qlat2, Q_LORA, Q_LORA);
    rmsnorm_split<<<S_LEN, 256>>>(kv, kvnw, ckv2, KV_LORA, KV_IN);
    gemm_bf16_tn<<<dim3(QB_OUT / 128, S_LEN / 128, 1), blk>>>(
        qlat2, wqb2, qfull, S_LEN, QB_OUT, Q_LORA);
    gemm_bf16_tn<<<dim3(KVB_OUT / 128, S_LEN / 128, 1), blk>>>(
        ckv2, wkvb2, kvexp, S_LEN, KVB_OUT, KV_LORA);

    // assemble attention operands
    assemble_q<<<dim3(S_LEN, NH), Q_HEAD>>>(softmax_scale);
    assemble_k<<<dim3(S_LEN, NH), Q_HEAD>>>();
    assemble_vt<<<dim3(S_LEN / 32, V_DIM / 32, NH), dim3(32, 32)>>>();

    // fused flash attention -> attn2
    flash_attn<<<dim3(8, NH), blk, FL_SMEM>>>();

    // output projection
    gemm_bf16_tn<<<dim3(HID / 128, S_LEN / 128, 1), blk>>>(
        attn2, wo2, out, S_LEN, HID, NH * V_DIM);
}

// round 8
// speedup vs baseline: 1.4511x; 1.1668x over previous
#include <cuda_runtime.h>
#include <cuda_bf16.h>
#include <math.h>
#include <stdint.h>

// ---------------------------------------------------------------------------
// Problem constants
// ---------------------------------------------------------------------------
#define S_LEN   2048
#define HID     4096
#define Q_LORA  1536
#define KV_LORA 512
#define KV_IN   576
#define QKV_W   (Q_LORA + KV_IN)         // 2112 combined qkv-a output width
#define NH      16
#define QK_NOPE 128
#define QK_ROPE 64
#define Q_HEAD  192
#define V_DIM   128
#define QB_OUT  (NH * Q_HEAD)            // 3072
#define KVB_OUT (NH * (QK_NOPE + V_DIM)) // 4096
#define RMS_EPS 1e-6f
#define ROPE_BASE 10000.0f

typedef __nv_bfloat16 bf16;

// ---------------------------------------------------------------------------
// Static device scratch (split-2 [hi|lo] storage; GEMMs do 3 logical segment
// products with maps A:{0,1,0}, B:{0,0,1})
// ---------------------------------------------------------------------------
__device__ float g_qkv_raw [S_LEN * QKV_W];      // [q_lat_raw | kv] combined
__device__ float g_qfull   [S_LEN * QB_OUT];
__device__ float g_kvexp   [S_LEN * KVB_OUT];

__device__ bf16 g_hidden2 [(size_t)S_LEN * 2 * HID];
__device__ bf16 g_wqkva2  [(size_t)QKV_W * 2 * HID];   // wq_a rows then wkv_a rows
__device__ bf16 g_qlat2   [(size_t)S_LEN * 2 * Q_LORA];
__device__ bf16 g_wqb2    [(size_t)QB_OUT * 2 * Q_LORA];
__device__ bf16 g_ckv2    [(size_t)S_LEN * 2 * KV_LORA];
__device__ bf16 g_wkvb2   [(size_t)KVB_OUT * 2 * KV_LORA];
__device__ bf16 g_Q2      [(size_t)NH * S_LEN * 2 * Q_HEAD];
__device__ bf16 g_K2      [(size_t)NH * S_LEN * 2 * Q_HEAD];
__device__ bf16 g_Vt2     [(size_t)NH * V_DIM * 2 * S_LEN];
__device__ bf16 g_attn2   [(size_t)S_LEN * 2 * (NH * V_DIM)];
__device__ bf16 g_wo2     [(size_t)HID * 2 * (NH * V_DIM)];

// ---------------------------------------------------------------------------
// helpers
// ---------------------------------------------------------------------------
__device__ __forceinline__ uint32_t smem_u32(const void* p) {
    return (uint32_t)__cvta_generic_to_shared(p);
}
__device__ __forceinline__ void ldsm_x4(uint32_t& r0, uint32_t& r1,
                                        uint32_t& r2, uint32_t& r3, uint32_t addr) {
    asm volatile("ldmatrix.sync.aligned.m8n8.x4.shared.b16 {%0,%1,%2,%3}, [%4];"
                 : "=r"(r0), "=r"(r1), "=r"(r2), "=r"(r3) : "r"(addr));
}
__device__ __forceinline__ void mma16816(float* c, const uint32_t* a, const uint32_t* b) {
    asm volatile("mma.sync.aligned.m16n8k16.row.col.f32.bf16.bf16.f32 "
                 "{%0,%1,%2,%3}, {%4,%5,%6,%7}, {%8,%9}, {%0,%1,%2,%3};"
                 : "+f"(c[0]), "+f"(c[1]), "+f"(c[2]), "+f"(c[3])
                 : "r"(a[0]), "r"(a[1]), "r"(a[2]), "r"(a[3]),
                   "r"(b[0]), "r"(b[1]));
}
__device__ __forceinline__ void split2(float v, bf16& h, bf16& l) {
    h = __float2bfloat16(v);
    l = __float2bfloat16(v - __bfloat162float(h));
}

// ---------------------------------------------------------------------------
// Dense bf16 TN GEMM: split-2 storage + 3 logical products.
// B fragments loaded via ldmatrix.x4 (both k-halves per instruction).
// ---------------------------------------------------------------------------
#define GBM 128
#define GBK 32
#define SMPAD 40

__global__ __launch_bounds__(256, 2)
void gemm_bf16_tn(const bf16* __restrict__ A, const bf16* __restrict__ B,
                  float* __restrict__ C, int M, int N, int Kb)
{
    const int bm = blockIdx.y * GBM;
    const int bn = blockIdx.x * GBM;

    __shared__ bf16 As[2][GBM][SMPAD];
    __shared__ bf16 Bs[2][GBM][SMPAD];

    const int tid  = threadIdx.x;
    const int lane = tid & 31;
    const int wid  = tid >> 5;
    const int wm   = (wid >> 2) * 64;
    const int wn   = (wid & 3) * 32;
    const int gid  = lane >> 2;
    const int tig  = lane & 3;

    const int lr = tid >> 2;
    const int lc = (tid & 3) * 8;

    float acc[4][4][4];
#pragma unroll
    for (int a = 0; a < 4; a++)
#pragma unroll
        for (int b = 0; b < 4; b++)
#pragma unroll
            for (int c = 0; c < 4; c++) acc[a][b][c] = 0.f;

    const int rowlen = 2 * Kb;
    const int per_seg = Kb / GBK;
    const int ntiles = 3 * per_seg;

    uint4 av0, av1, bv0, bv1;
    auto glob_load = [&](int i) {
        const int seg = i / per_seg;
        const int w   = i - seg * per_seg;
        const int kA  = ((seg == 1) ? Kb : 0) + w * GBK;
        const int kB  = ((seg == 2) ? Kb : 0) + w * GBK;
        const bf16* Ap = A + (size_t)(bm + lr) * rowlen + kA + lc;
        av0 = *(const uint4*)Ap;
        av1 = *(const uint4*)(Ap + (size_t)64 * rowlen);
        const int n0 = bn + lr;
        const bf16* Bp = B + (size_t)n0 * rowlen + kB + lc;
        bv0 = (n0      < N) ? *(const uint4*)Bp                         : make_uint4(0,0,0,0);
        bv1 = (n0 + 64 < N) ? *(const uint4*)(Bp + (size_t)64 * rowlen) : make_uint4(0,0,0,0);
    };
    auto sts = [&](int buf) {
        *(uint4*)&As[buf][lr     ][lc] = av0;
        *(uint4*)&As[buf][lr + 64][lc] = av1;
        *(uint4*)&Bs[buf][lr     ][lc] = bv0;
        *(uint4*)&Bs[buf][lr + 64][lc] = bv1;
    };

    const uint32_t as_base = smem_u32(&As[0][0][0]);
    const uint32_t bs_base = smem_u32(&Bs[0][0][0]);
    const uint32_t BUFB = GBM * SMPAD * 2;

    const int a_row  = wm + (lane & 15);
    const int a_col  = (lane >> 4) * 8;
    const int b_row  = wn + (lane & 7);
    const int b_col4 = (lane >> 4) * 16 + ((lane >> 3) & 1) * 8;

    auto compute = [&](int buf) {
        uint32_t bq[4][4];
#pragma unroll
        for (int nt = 0; nt < 4; nt++) {
            uint32_t addr = bs_base + buf * BUFB +
                (uint32_t)(((b_row + nt * 8) * SMPAD + b_col4) * 2);
            ldsm_x4(bq[nt][0], bq[nt][1], bq[nt][2], bq[nt][3], addr);
        }
#pragma unroll
        for (int ks = 0; ks < 2; ks++) {
            uint32_t af[4][4];
#pragma unroll
            for (int mt = 0; mt < 4; mt++) {
                uint32_t addr = as_base + buf * BUFB +
                    (uint32_t)(((a_row + mt * 16) * SMPAD + ks * 16 + a_col) * 2);
                ldsm_x4(af[mt][0], af[mt][1], af[mt][2], af[mt][3], addr);
            }
#pragma unroll
            for (int mt = 0; mt < 4; mt++)
#pragma unroll
                for (int nt = 0; nt < 4; nt++)
                    mma16816(acc[mt][nt], af[mt], &bq[nt][ks * 2]);
        }
    };

    glob_load(0);
    sts(0);
    __syncthreads();
    int buf = 0;
    for (int kt = 0; kt < ntiles; kt++) {
        if (kt + 1 < ntiles) glob_load(kt + 1);
        compute(buf);
        if (kt + 1 < ntiles) {
            sts(buf ^ 1);
            __syncthreads();
            buf ^= 1;
        }
    }

#pragma unroll
    for (int mt = 0; mt < 4; mt++) {
        const int row = bm + wm + mt * 16 + gid;
#pragma unroll
        for (int nt = 0; nt < 4; nt++) {
            const int col = bn + wn + nt * 8 + tig * 2;
            if (col < N) {
                *(float2*)&C[(size_t)row * N + col] =
                    make_float2(acc[mt][nt][0], acc[mt][nt][1]);
                *(float2*)&C[(size_t)(row + 8) * N + col] =
                    make_float2(acc[mt][nt][2], acc[mt][nt][3]);
            }
        }
    }
}

// ---------------------------------------------------------------------------
// Fused flash attention (split-2 operands, online softmax).
// Grid (8, NH): CTA handles q-tiles qb and 15-qb (uniform 17 k-iterations).
// ---------------------------------------------------------------------------
#define FL_AS   0
#define FL_BS   20480
#define FL_PS   40960                    // Ps: 128 x 264 halves (hi|lo + pad)
#define FL_WMAX 108544
#define FL_WSUM 110592
#define FL_RM   112640
#define FL_RL   113152
#define FL_RC   113664
#define FL_SMEM 114176
#define PS_LDA  264

__global__ __launch_bounds__(256)
void flash_attn()
{
    extern __shared__ char sm[];
    const uint32_t sb = smem_u32(sm);
    float* wmax  = (float*)(sm + FL_WMAX);
    float* wsum  = (float*)(sm + FL_WSUM);
    float* row_m = (float*)(sm + FL_RM);
    float* row_l = (float*)(sm + FL_RL);
    float* row_c = (float*)(sm + FL_RC);
    bf16*  Ps    = (bf16*)(sm + FL_PS);

    const int h    = blockIdx.y;
    const int tid  = threadIdx.x;
    const int lane = tid & 31;
    const int wid  = tid >> 5;
    const int wm   = (wid >> 2) * 64;
    const int wn   = (wid & 3) * 32;
    const int gid  = lane >> 2;
    const int tig  = lane & 3;
    const int lr   = tid >> 2;
    const int lc   = (tid & 3) * 8;
    const int wq   = wid & 3;

    const bf16* Qh = g_Q2 + (size_t)h * S_LEN * (2 * Q_HEAD);
    const bf16* Kh = g_K2 + (size_t)h * S_LEN * (2 * Q_HEAD);
    const bf16* Vh = g_Vt2 + (size_t)h * V_DIM * (2 * S_LEN);

    const int a_row  = wm + (lane & 15);
    const int a_col  = (lane >> 4) * 8;
    const int b_row  = wn + (lane & 7);
    const int b_col4 = (lane >> 4) * 16 + ((lane >> 3) & 1) * 8;
    const uint32_t BUFB = 128 * SMPAD * 2;

    for (int half = 0; half < 2; half++) {
        const int qb = half ? (15 - (int)blockIdx.x) : (int)blockIdx.x;
        const int q0 = qb * 128;

        if (tid < 128) { row_m[tid] = -1e30f; row_l[tid] = 0.f; }
        float acc_o[4][4][4];
#pragma unroll
        for (int a = 0; a < 4; a++)
#pragma unroll
            for (int b = 0; b < 4; b++)
#pragma unroll
                for (int c = 0; c < 4; c++) acc_o[a][b][c] = 0.f;
        __syncthreads();

        for (int jb = 0; jb <= qb; jb++) {
            // ================= S = Q K^T (18 k-tiles, segment remap) =======
            float acc_s[4][4][4];
#pragma unroll
            for (int a = 0; a < 4; a++)
#pragma unroll
                for (int b = 0; b < 4; b++)
#pragma unroll
                    for (int c = 0; c < 4; c++) acc_s[a][b][c] = 0.f;

            uint4 av0, av1, bv0, bv1;
            auto gload = [&](int i) {
                const int seg = i / 6, w = i - seg * 6;
                const int kA = ((seg == 1) ? Q_HEAD : 0) + w * 32;
                const int kB = ((seg == 2) ? Q_HEAD : 0) + w * 32;
                const bf16* Ap = Qh + (size_t)(q0 + lr) * 384 + kA + lc;
                const bf16* Bp = Kh + (size_t)(jb * 128 + lr) * 384 + kB + lc;
                av0 = *(const uint4*)Ap;
                av1 = *(const uint4*)(Ap + (size_t)64 * 384);
                bv0 = *(const uint4*)Bp;
                bv1 = *(const uint4*)(Bp + (size_t)64 * 384);
            };
            auto sts = [&](int buf) {
                *(uint4*)(sm + FL_AS + buf * BUFB + (uint32_t)((lr * SMPAD + lc) * 2))        = av0;
                *(uint4*)(sm + FL_AS + buf * BUFB + (uint32_t)(((lr + 64) * SMPAD + lc) * 2)) = av1;
                *(uint4*)(sm + FL_BS + buf * BUFB + (uint32_t)((lr * SMPAD + lc) * 2))        = bv0;
                *(uint4*)(sm + FL_BS + buf * BUFB + (uint32_t)(((lr + 64) * SMPAD + lc) * 2)) = bv1;
            };
            auto computeS = [&](int buf) {
                uint32_t bq[4][4];
#pragma unroll
                for (int nt = 0; nt < 4; nt++) {
                    uint32_t addr = sb + FL_BS + buf * BUFB +
                        (uint32_t)(((b_row + nt * 8) * SMPAD + b_col4) * 2);
                    ldsm_x4(bq[nt][0], bq[nt][1], bq[nt][2], bq[nt][3], addr);
                }
#pragma unroll
                for (int ks = 0; ks < 2; ks++) {
                    uint32_t af[4][4];
#pragma unroll
                    for (int mt = 0; mt < 4; mt++) {
                        uint32_t addr = sb + FL_AS + buf * BUFB +
                            (uint32_t)(((a_row + mt * 16) * SMPAD + ks * 16 + a_col) * 2);
                        ldsm_x4(af[mt][0], af[mt][1], af[mt][2], af[mt][3], addr);
                    }
#pragma unroll
                    for (int mt = 0; mt < 4; mt++)
#pragma unroll
                        for (int nt = 0; nt < 4; nt++)
                            mma16816(acc_s[mt][nt], af[mt], &bq[nt][ks * 2]);
                }
            };

            gload(0); sts(0); __syncthreads();
            int buf = 0;
            for (int kt = 0; kt < 18; kt++) {
                if (kt + 1 < 18) gload(kt + 1);
                computeS(buf);
                if (kt + 1 < 18) { sts(buf ^ 1); __syncthreads(); buf ^= 1; }
            }

            // ================= mask (diagonal block) ========================
            if (jb == qb) {
#pragma unroll
                for (int mt = 0; mt < 4; mt++) {
                    const int m0 = wm + mt * 16 + gid;
#pragma unroll
                    for (int nt = 0; nt < 4; nt++) {
                        const int n0 = wn + nt * 8 + tig * 2;
                        if (n0     > m0    ) acc_s[mt][nt][0] = -1e30f;
                        if (n0 + 1 > m0    ) acc_s[mt][nt][1] = -1e30f;
                        if (n0     > m0 + 8) acc_s[mt][nt][2] = -1e30f;
                        if (n0 + 1 > m0 + 8) acc_s[mt][nt][3] = -1e30f;
                    }
                }
            }
            __syncthreads();

            // ================= row max ======================================
            float rmx[4][2];
#pragma unroll
            for (int mt = 0; mt < 4; mt++) {
                float m0 = -1e30f, m1 = -1e30f;
#pragma unroll
                for (int nt = 0; nt < 4; nt++) {
                    m0 = fmaxf(m0, fmaxf(acc_s[mt][nt][0], acc_s[mt][nt][1]));
                    m1 = fmaxf(m1, fmaxf(acc_s[mt][nt][2], acc_s[mt][nt][3]));
                }
                rmx[mt][0] = m0; rmx[mt][1] = m1;
            }
#pragma unroll
            for (int o = 1; o < 4; o <<= 1)
#pragma unroll
                for (int mt = 0; mt < 4; mt++) {
                    rmx[mt][0] = fmaxf(rmx[mt][0], __shfl_xor_sync(0xffffffffu, rmx[mt][0], o));
                    rmx[mt][1] = fmaxf(rmx[mt][1], __shfl_xor_sync(0xffffffffu, rmx[mt][1], o));
                }
            if (tig == 0) {
#pragma unroll
                for (int mt = 0; mt < 4; mt++) {
                    wmax[wq * 128 + wm + mt * 16 + gid]     = rmx[mt][0];
                    wmax[wq * 128 + wm + mt * 16 + gid + 8] = rmx[mt][1];
                }
            }
            __syncthreads();

            // ========== P = exp(S-new_m), write Ps (hi|lo), partial sums ====
            float psum[4][2];
#pragma unroll
            for (int mt = 0; mt < 4; mt++) {
#pragma unroll
                for (int rr = 0; rr < 2; rr++) {
                    const int r = wm + mt * 16 + gid + rr * 8;
                    float bmx = fmaxf(fmaxf(wmax[r], wmax[128 + r]),
                                      fmaxf(wmax[256 + r], wmax[384 + r]));
                    const float newm = fmaxf(row_m[r], bmx);
                    float s = 0.f;
#pragma unroll
                    for (int nt = 0; nt < 4; nt++) {
                        const int n0 = wn + nt * 8 + tig * 2;
                        float p0 = __expf(acc_s[mt][nt][rr * 2 + 0] - newm);
                        float p1 = __expf(acc_s[mt][nt][rr * 2 + 1] - newm);
                        s += p0 + p1;
                        bf16 h0, l0, h1, l1;
                        split2(p0, h0, l0); split2(p1, h1, l1);
                        __nv_bfloat162 hp, lp;
                        hp.x = h0; hp.y = h1; lp.x = l0; lp.y = l1;
                        *(__nv_bfloat162*)&Ps[r * PS_LDA + n0]       = hp;
                        *(__nv_bfloat162*)&Ps[r * PS_LDA + 128 + n0] = lp;
                    }
                    psum[mt][rr] = s;
                }
            }
#pragma unroll
            for (int o = 1; o < 4; o <<= 1)
#pragma unroll
                for (int mt = 0; mt < 4; mt++) {
                    psum[mt][0] += __shfl_xor_sync(0xffffffffu, psum[mt][0], o);
                    psum[mt][1] += __shfl_xor_sync(0xffffffffu, psum[mt][1], o);
                }
            if (tig == 0) {
#pragma unroll
                for (int mt = 0; mt < 4; mt++) {
                    wsum[wq * 128 + wm + mt * 16 + gid]     = psum[mt][0];
                    wsum[wq * 128 + wm + mt * 16 + gid + 8] = psum[mt][1];
                }
            }
            __syncthreads();

            // ================= per-row state update ========================
            if (tid < 128) {
                const int r = tid;
                float bmx = fmaxf(fmaxf(wmax[r], wmax[128 + r]),
                                  fmaxf(wmax[256 + r], wmax[384 + r]));
                const float old  = row_m[r];
                const float newm = fmaxf(old, bmx);
                const float corr = __expf(old - newm);
                const float bs = wsum[r] + wsum[128 + r] + wsum[256 + r] + wsum[384 + r];
                row_l[r] = row_l[r] * corr + bs;
                row_m[r] = newm;
                row_c[r] = corr;
            }
            __syncthreads();

#pragma unroll
            for (int mt = 0; mt < 4; mt++) {
                const float c0 = row_c[wm + mt * 16 + gid];
                const float c1 = row_c[wm + mt * 16 + gid + 8];
#pragma unroll
                for (int nt = 0; nt < 4; nt++) {
                    acc_o[mt][nt][0] *= c0; acc_o[mt][nt][1] *= c0;
                    acc_o[mt][nt][2] *= c1; acc_o[mt][nt][3] *= c1;
                }
            }

            // ================= O += P V  (12 k-tiles) ========================
            auto gloadV = [&](int t) {
                const int seg = t >> 2, w = t & 3;
                const int kB = ((seg == 2) ? S_LEN : 0) + jb * 128 + w * 32;
                const bf16* Bp = Vh + (size_t)lr * (2 * S_LEN) + kB + lc;
                bv0 = *(const uint4*)Bp;
                bv1 = *(const uint4*)(Bp + (size_t)64 * (2 * S_LEN));
            };
            auto stsV = [&](int b2) {
                *(uint4*)(sm + FL_BS + b2 * BUFB + (uint32_t)((lr * SMPAD + lc) * 2))        = bv0;
                *(uint4*)(sm + FL_BS + b2 * BUFB + (uint32_t)(((lr + 64) * SMPAD + lc) * 2)) = bv1;
            };
            auto computePV = [&](int t, int b2) {
                const int seg = t >> 2, w = t & 3;
                const int kA = ((seg == 1) ? 128 : 0) + w * 32;
                uint32_t bq[4][4];
#pragma unroll
                for (int nt = 0; nt < 4; nt++) {
                    uint32_t addr = sb + FL_BS + b2 * BUFB +
                        (uint32_t)(((b_row + nt * 8) * SMPAD + b_col4) * 2);
                    ldsm_x4(bq[nt][0], bq[nt][1], bq[nt][2], bq[nt][3], addr);
                }
#pragma unroll
                for (int ks = 0; ks < 2; ks++) {
                    uint32_t af[4][4];
#pragma unroll
                    for (int mt = 0; mt < 4; mt++) {
                        uint32_t addr = sb + FL_PS +
                            (uint32_t)(((a_row + mt * 16) * PS_LDA + kA + ks * 16 + a_col) * 2);
                        ldsm_x4(af[mt][0], af[mt][1], af[mt][2], af[mt][3], addr);
                    }
#pragma unroll
                    for (int mt = 0; mt < 4; mt++)
#pragma unroll
                        for (int nt = 0; nt < 4; nt++)
                            mma16816(acc_o[mt][nt], af[mt], &bq[nt][ks * 2]);
                }
            };

            gloadV(0); stsV(0); __syncthreads();
            for (int t = 0; t < 12; t++) {
                if (t + 1 < 12) gloadV(t + 1);
                computePV(t, t & 1);
                if (t + 1 < 12) { stsV((t & 1) ^ 1); __syncthreads(); }
            }
            __syncthreads();
        }

        // ================= epilogue: O / l -> attn2 (split-2) ===============
#pragma unroll
        for (int mt = 0; mt < 4; mt++) {
            const int r0 = wm + mt * 16 + gid;
            const int r1 = r0 + 8;
            const float inv0 = 1.f / row_l[r0];
            const float inv1 = 1.f / row_l[r1];
            bf16* d0 = g_attn2 + (size_t)(q0 + r0) * (2 * NH * V_DIM);
            bf16* d1 = g_attn2 + (size_t)(q0 + r1) * (2 * NH * V_DIM);
#pragma unroll
            for (int nt = 0; nt < 4; nt++) {
                const int c = h * V_DIM + wn + nt * 8 + tig * 2;
                bf16 h0, l0, h1, l1;
                split2(acc_o[mt][nt][0] * inv0, h0, l0);
                split2(acc_o[mt][nt][1] * inv0, h1, l1);
                __nv_bfloat162 hp, lp;
                hp.x = h0; hp.y = h1; lp.x = l0; lp.y = l1;
                *(__nv_bfloat162*)&d0[c]              = hp;
                *(__nv_bfloat162*)&d0[NH * V_DIM + c] = lp;
                split2(acc_o[mt][nt][2] * inv1, h0, l0);
                split2(acc_o[mt][nt][3] * inv1, h1, l1);
                hp.x = h0; hp.y = h1; lp.x = l0; lp.y = l1;
                *(__nv_bfloat162*)&d1[c]              = hp;
                *(__nv_bfloat162*)&d1[NH * V_DIM + c] = lp;
            }
        }
        __syncthreads();
    }
}

// ---------------------------------------------------------------------------
// fp32 -> bf16 split-2 rows
// ---------------------------------------------------------------------------
__global__ __launch_bounds__(256)
void split2_rows(const float* __restrict__ x, bf16* __restrict__ y, int C)
{
    const int row = blockIdx.x;
    const float* xr = x + (size_t)row * C;
    bf16* yr = y + (size_t)row * 2 * C;
    for (int j = threadIdx.x * 4; j < C; j += 256 * 4) {
        float4 v = *(const float4*)&xr[j];
        bf16 h0, l0, h1, l1, h2, l2, h3, l3;
        split2(v.x, h0, l0); split2(v.y, h1, l1);
        split2(v.z, h2, l2); split2(v.w, h3, l3);
        __nv_bfloat162 hh01, hh23, ll01, ll23;
        hh01.x = h0; hh01.y = h1; hh23.x = h2; hh23.y = h3;
        ll01.x = l0; ll01.y = l1; ll23.x = l2; ll23.y = l3;
        *(__nv_bfloat162*)&yr[j]         = hh01;
        *(__nv_bfloat162*)&yr[j + 2]     = hh23;
        *(__nv_bfloat162*)&yr[C + j]     = ll01;
        *(__nv_bfloat162*)&yr[C + j + 2] = ll23;
    }
}

// ---------------------------------------------------------------------------
// RMSNorm fused with split-2 output
// ---------------------------------------------------------------------------
__global__ __launch_bounds__(256)
void rmsnorm_split(const float* __restrict__ x, const float* __restrict__ w,
                   bf16* __restrict__ y2, int len, int xstride)
{
    const int row = blockIdx.x;
    const float* xr = x + (size_t)row * xstride;
    bf16* yr = y2 + (size_t)row * 2 * len;

    float ss = 0.f;
    for (int j = threadIdx.x; j < len; j += 256) { float v = xr[j]; ss += v * v; }
    __shared__ float red[256];
    red[threadIdx.x] = ss;
    __syncthreads();
    for (int s = 128; s > 0; s >>= 1) {
        if (threadIdx.x < s) red[threadIdx.x] += red[threadIdx.x + s];
        __syncthreads();
    }
    const float inv = rsqrtf(red[0] / (float)len + RMS_EPS);
    for (int j = threadIdx.x; j < len; j += 256) {
        bf16 h, l;
        split2(w[j] * xr[j] * inv, h, l);
        yr[j] = h; yr[len + j] = l;
    }
}

// ---------------------------------------------------------------------------
// RoPE + assembles
// ---------------------------------------------------------------------------
__device__ __forceinline__ void rope_cs(int pos, int jj, float& c, float& s)
{
    int i = jj & 31;
    float inv = __expf(-((float)(2 * i) / (float)QK_ROPE) * logf(ROPE_BASE));
    float ang = (float)pos * inv;
    c = cosf(ang);
    s = sinf(ang);
}

__global__ void assemble_q(float scale)
{
    const int s = blockIdx.x, h = blockIdx.y, j = threadIdx.x;
    const float* src = g_qfull + (size_t)s * QB_OUT + h * Q_HEAD;
    float v = src[j];
    if (j >= QK_NOPE) {
        int jj = j - QK_NOPE;
        float c, sn;
        rope_cs(s, jj, c, sn);
        float other = (jj < 32) ? -src[QK_NOPE + jj + 32] : src[QK_NOPE + jj - 32];
        v = v * c + other * sn;
    }
    v *= scale;
    bf16 hh, ll;
    split2(v, hh, ll);
    bf16* dst = g_Q2 + ((size_t)h * S_LEN + s) * 2 * Q_HEAD;
    dst[j] = hh; dst[Q_HEAD + j] = ll;
}

__global__ void assemble_k()
{
    const int s = blockIdx.x, h = blockIdx.y, j = threadIdx.x;
    float v;
    if (j < QK_NOPE) {
        v = g_kvexp[(size_t)s * KVB_OUT + h * (QK_NOPE + V_DIM) + j];
    } else {
        int jj = j - QK_NOPE;
        const float* pe = g_qkv_raw + (size_t)s * QKV_W + Q_LORA + KV_LORA;
        float c, sn;
        rope_cs(s, jj, c, sn);
        float other = (jj < 32) ? -pe[jj + 32] : pe[jj - 32];
        v = pe[jj] * c + other * sn;
    }
    bf16 hh, ll;
    split2(v, hh, ll);
    bf16* dst = g_K2 + ((size_t)h * S_LEN + s) * 2 * Q_HEAD;
    dst[j] = hh; dst[Q_HEAD + j] = ll;
}

__global__ void assemble_vt()
{
    __shared__ float sm[32][33];
    const int h = blockIdx.z;
    const int s0 = blockIdx.x * 32, d0 = blockIdx.y * 32;
    const int tx = threadIdx.x, ty = threadIdx.y;
    sm[ty][tx] = g_kvexp[(size_t)(s0 + ty) * KVB_OUT +
                         h * (QK_NOPE + V_DIM) + QK_NOPE + d0 + tx];
    __syncthreads();
    const int d = d0 + ty, s = s0 + tx;
    bf16 hh, ll;
    split2(sm[tx][ty], hh, ll);
    bf16* dst = g_Vt2 + ((size_t)h * V_DIM + d) * 2 * S_LEN;
    dst[s] = hh; dst[S_LEN + s] = ll;
}

// ---------------------------------------------------------------------------
// Host launch
// ---------------------------------------------------------------------------
extern "C" void kernel_launch(void* const* d_in, const int* in_sizes, int n_in,
                              void* d_out, int out_size)
{
    (void)in_sizes; (void)n_in; (void)out_size;
    const float* hidden = (const float*)d_in[0];
    const float* wq_a   = (const float*)d_in[2];
    const float* qnw    = (const float*)d_in[3];
    const float* wq_b   = (const float*)d_in[4];
    const float* wkv_a  = (const float*)d_in[5];
    const float* kvnw   = (const float*)d_in[6];
    const float* wkv_b  = (const float*)d_in[7];
    const float* wo     = (const float*)d_in[8];
    float* out = (float*)d_out;

    float *qkv_raw, *qfull, *kvexp;
    bf16 *hidden2, *wqkva2, *qlat2, *wqb2, *ckv2, *wkvb2, *attn2, *wo2;
    cudaGetSymbolAddress((void**)&qkv_raw, g_qkv_raw);
    cudaGetSymbolAddress((void**)&qfull,   g_qfull);
    cudaGetSymbolAddress((void**)&kvexp,   g_kvexp);
    cudaGetSymbolAddress((void**)&hidden2, g_hidden2);
    cudaGetSymbolAddress((void**)&wqkva2,  g_wqkva2);
    cudaGetSymbolAddress((void**)&qlat2,   g_qlat2);
    cudaGetSymbolAddress((void**)&wqb2,    g_wqb2);
    cudaGetSymbolAddress((void**)&ckv2,    g_ckv2);
    cudaGetSymbolAddress((void**)&wkvb2,   g_wkvb2);
    cudaGetSymbolAddress((void**)&attn2,   g_attn2);
    cudaGetSymbolAddress((void**)&wo2,     g_wo2);

    const float softmax_scale = rsqrtf((float)Q_HEAD);
    dim3 blk(256);

    cudaFuncSetAttribute(flash_attn, cudaFuncAttributeMaxDynamicSharedMemorySize,
                         FL_SMEM);

    // split-2 of inputs / weights (wq_a + wkv_a into one combined B buffer)
    split2_rows<<<S_LEN,   256>>>(hidden, hidden2, HID);
    split2_rows<<<Q_LORA,  256>>>(wq_a,  wqkva2, HID);
    split2_rows<<<KV_IN,   256>>>(wkv_a, wqkva2 + (size_t)Q_LORA * 2 * HID, HID);
    split2_rows<<<QB_OUT,  256>>>(wq_b,  wqb2,  Q_LORA);
    split2_rows<<<KVB_OUT, 256>>>(wkv_b, wkvb2, KV_LORA);
    split2_rows<<<HID,     256>>>(wo,    wo2,   NH * V_DIM);

    // 1+2 fused: [q_lat_raw | kv] = hidden @ [wq_a | wkv_a]^T   (N=2112)
    gemm_bf16_tn<<<dim3((QKV_W + 127) / 128, S_LEN / 128, 1), blk>>>(
        hidden2, wqkva2, qkv_raw, S_LEN, QKV_W, HID);
    // 3-4. RMSNorms with fused split (reading combined buffer)
    rmsnorm_split<<<S_LEN, 256>>>(qkv_raw, qnw, qlat2, Q_LORA, QKV_W);
    rmsnorm_split<<<S_LEN, 256>>>(qkv_raw + Q_LORA, kvnw, ckv2, KV_LORA, QKV_W);
    // 5. q = q_lat @ wq_b^T
    gemm_bf16_tn<<<dim3(QB_OUT / 128, S_LEN / 128, 1), blk>>>(
        qlat2, wqb2, qfull, S_LEN, QB_OUT, Q_LORA);
    // 6. kv_exp = ckv @ wkv_b^T
    gemm_bf16_tn<<<dim3(KVB_OUT / 128, S_LEN / 128, 1), blk>>>(
        ckv2, wkvb2, kvexp, S_LEN, KVB_OUT, KV_LORA);

    // assemble attention operands
    assemble_q<<<dim3(S_LEN, NH), Q_HEAD>>>(softmax_scale);
    assemble_k<<<dim3(S_LEN, NH), Q_HEAD>>>();
    assemble_vt<<<dim3(S_LEN / 32, V_DIM / 32, NH), dim3(32, 32)>>>();

    // fused flash attention -> attn2
    flash_attn<<<dim3(8, NH), blk, FL_SMEM>>>();

    // output projection
    gemm_bf16_tn<<<dim3(HID / 128, S_LEN / 128, 1), blk>>>(
        attn2, wo2, out, S_LEN, HID, NH * V_DIM);
}